// round 11
// baseline (speedup 1.0000x reference)
#include <cuda_runtime.h>
#include <cuda_fp16.h>
#include <math.h>

// Problem constants (fixed by the reference)
#define NN   100000
#define EE   1600000
#define BN_EPS 1e-5f
#define SLOPE 0.2f

// ---------------- scratch (device globals; no allocation allowed) ----------
__device__ __half2 g_h16[(size_t)NN * 64];   // h in fp16 (128 halfs/row; L2: 40)
__device__ float  g_bufB[(size_t)NN * 128];  // gather output (fp32, BN input)
__device__ float  g_als[NN * 2];
__device__ float  g_ald[NN * 2];
__device__ float  g_ew0[EE];                 // per-edge exp weights, head 0
__device__ float  g_ew1[EE];                 // head 1
__device__ int    g_deg[NN];
__device__ int    g_rowptr[NN + 1];
__device__ int    g_cursor[NN];
__device__ int    g_perm_src[EE];
__device__ int    g_perm_dst[EE];
__device__ int    g_bsum[128];
__device__ int    g_is64;
__device__ float  g_acc0[256];               // BN accum layer 0 (zeroed in init)
__device__ float  g_acc1[256];               // BN accum layer 1
__device__ float  g_stats[256];  // [0:128) scale, [128:256) shift (current)

// ---------------- f32x2 helpers (FFMA2: 2x fp32 FMA per instruction) -------
__device__ __forceinline__ unsigned long long pk2(float lo, float hi) {
    unsigned long long r;
    asm("mov.b64 %0, {%1,%2};" : "=l"(r) : "f"(lo), "f"(hi));
    return r;
}
__device__ __forceinline__ void ffma2(unsigned long long& d,
                                      unsigned long long a, unsigned long long b) {
    asm("fma.rn.f32x2 %0, %1, %2, %0;" : "+l"(d) : "l"(a), "l"(b));
}
__device__ __forceinline__ float2 upk2(unsigned long long v) {
    float2 f;
    asm("mov.b64 {%0,%1}, %2;" : "=f"(f.x), "=f"(f.y) : "l"(v));
    return f;
}

// ---------------- init: dtype detect + zero deg + zero BN accumulators -----
__global__ void k_init(const int* __restrict__ w) {
    int i = blockIdx.x * blockDim.x + threadIdx.x;
    if (i < NN) g_deg[i] = 0;
    if (blockIdx.x == 0) {
        __shared__ int nz;
        if (threadIdx.x == 0) nz = 0;
        if (threadIdx.x < 256) {
            g_acc0[threadIdx.x] = 0.f;
            g_acc1[threadIdx.x] = 0.f;
        }
        __syncthreads();
        for (int j = threadIdx.x; j < 1024; j += blockDim.x)
            if (w[2 * j + 1] != 0) nz = 1;
        __syncthreads();
        if (threadIdx.x == 0) g_is64 = nz ? 0 : 1;
    }
}

// ---------------- CSR build ------------------------------------------------
__global__ void k_count(const int* __restrict__ w) {
    int t = blockIdx.x * blockDim.x + threadIdx.x;
    int base = t * 4;
    int is64 = g_is64;
    #pragma unroll
    for (int i = 0; i < 4; i++) {
        int e = base + i;
        if (e < EE) {
            int d = is64 ? w[2 * EE + 2 * e] : w[EE + e];
            if ((unsigned)d >= NN) d = 0;
            atomicAdd(&g_deg[d], 1);
        }
    }
}

__global__ void k_scan1() {
    __shared__ int sh[1024];
    int t = threadIdx.x;
    int i = blockIdx.x * 1024 + t;
    int v = (i < NN) ? g_deg[i] : 0;
    sh[t] = v;
    __syncthreads();
    #pragma unroll
    for (int off = 1; off < 1024; off <<= 1) {
        int x = (t >= off) ? sh[t - off] : 0;
        __syncthreads();
        sh[t] += x;
        __syncthreads();
    }
    if (i < NN) g_rowptr[i] = sh[t] - v;
    if (t == 1023) g_bsum[blockIdx.x] = sh[t];
}

// scan2 merged into scan3: each block locally scans the 98-entry bsum array
__global__ void k_scan23(int nb) {
    __shared__ int pre[128];
    __shared__ int total;
    int t = threadIdx.x;
    if (t < nb) pre[t] = g_bsum[t];
    __syncthreads();
    if (t == 0) {
        int run = 0;
        for (int b = 0; b < nb; b++) {
            int x = pre[b];
            pre[b] = run;
            run += x;
        }
        total = run;
    }
    __syncthreads();
    int i = blockIdx.x * blockDim.x + t;
    if (i < NN) {
        int v = g_rowptr[i] + pre[i >> 10];
        g_rowptr[i] = v;
        g_cursor[i] = v;
    }
    if (i == 0) g_rowptr[NN] = total;
}

__global__ void k_scatter(const int* __restrict__ w) {
    int t = blockIdx.x * blockDim.x + threadIdx.x;
    int base = t * 4;
    int is64 = g_is64;
    #pragma unroll
    for (int i = 0; i < 4; i++) {
        int e = base + i;
        if (e < EE) {
            int s, d;
            if (is64) {
                s = w[2 * e];
                d = w[2 * EE + 2 * e];
            } else {
                s = w[e];
                d = w[EE + e];
            }
            if ((unsigned)s >= NN) s = 0;
            if ((unsigned)d >= NN) d = 0;
            int pos = atomicAdd(&g_cursor[d], 1);
            g_perm_src[pos] = s;
            g_perm_dst[pos] = d;
        }
    }
}

// ---------------- edge weights: ew = exp(leaky(als[src] + ald[dst])) -------
__global__ void ew2_kernel() {
    int t = blockIdx.x * blockDim.x + threadIdx.x;
    int base = t * 4;
    #pragma unroll
    for (int i = 0; i < 4; i++) {
        int p = base + i;
        if (p < EE) {
            int s = g_perm_src[p];
            int d = g_perm_dst[p];
            float2 as = *(const float2*)&g_als[s * 2];
            float2 ad = *(const float2*)&g_ald[d * 2];
            float v0 = as.x + ad.x; v0 = v0 > 0.f ? v0 : SLOPE * v0;
            float v1 = as.y + ad.y; v1 = v1 > 0.f ? v1 : SLOPE * v1;
            g_ew0[p] = __expf(v0);
            g_ew1[p] = __expf(v1);
        }
    }
}

__global__ void ew1_kernel() {
    int t = blockIdx.x * blockDim.x + threadIdx.x;
    int base = t * 4;
    #pragma unroll
    for (int i = 0; i < 4; i++) {
        int p = base + i;
        if (p < EE) {
            int s = g_perm_src[p];
            int d = g_perm_dst[p];
            float v0 = g_als[s] + g_ald[d];
            v0 = v0 > 0.f ? v0 : SLOPE * v0;
            g_ew0[p] = __expf(v0);
        }
    }
}

// ---------------- GEMM 128x128: FFMA2, prefetch, BN+ReLU in, fp16 out, al --
template <bool TRANS>
__global__ __launch_bounds__(256)
void gemm128_kernel(const float* __restrict__ A, const float* __restrict__ W,
                    __half2* __restrict__ C,
                    const float* __restrict__ asrc, const float* __restrict__ adst,
                    int n) {
    constexpr int K = 128, BM = 128, BK = 16, BMP = 132;
    __shared__ float sA[BK][BMP];
    __shared__ float sW[BK][128];

    int tid = threadIdx.x;
    int tx = tid & 15, ty = tid >> 4;
    int row0 = blockIdx.x * BM;

    int lr = tid >> 2, lq = tid & 3;
    int lk = tid >> 5, lc = tid & 31;

    unsigned long long acc[8][4];
    #pragma unroll
    for (int r = 0; r < 8; r++)
        #pragma unroll
        for (int c = 0; c < 4; c++) acc[r][c] = 0ULL;

    float4 pa[2], pw[2];
    #pragma unroll
    for (int i = 0; i < 2; i++) {
        int gr = row0 + lr + i * 64;
        float4 v = make_float4(0.f, 0.f, 0.f, 0.f);
        if (gr < n) v = *(const float4*)&A[(size_t)gr * K + lq * 4];
        if (TRANS) {
            int f = lq * 4;
            v.x = fmaxf(v.x * g_stats[f + 0] + g_stats[128 + f + 0], 0.f);
            v.y = fmaxf(v.y * g_stats[f + 1] + g_stats[128 + f + 1], 0.f);
            v.z = fmaxf(v.z * g_stats[f + 2] + g_stats[128 + f + 2], 0.f);
            v.w = fmaxf(v.w * g_stats[f + 3] + g_stats[128 + f + 3], 0.f);
        }
        pa[i] = v;
        pw[i] = *(const float4*)&W[(size_t)(lk + i * 8) * 128 + lc * 4];
    }

    for (int k0 = 0; k0 < K; k0 += BK) {
        __syncthreads();
        #pragma unroll
        for (int i = 0; i < 2; i++) {
            sA[lq * 4 + 0][lr + i * 64] = pa[i].x;
            sA[lq * 4 + 1][lr + i * 64] = pa[i].y;
            sA[lq * 4 + 2][lr + i * 64] = pa[i].z;
            sA[lq * 4 + 3][lr + i * 64] = pa[i].w;
            *(float4*)&sW[lk + i * 8][lc * 4] = pw[i];
        }
        __syncthreads();
        if (k0 + BK < K) {
            int kn = k0 + BK;
            #pragma unroll
            for (int i = 0; i < 2; i++) {
                int gr = row0 + lr + i * 64;
                float4 v = make_float4(0.f, 0.f, 0.f, 0.f);
                if (gr < n) v = *(const float4*)&A[(size_t)gr * K + kn + lq * 4];
                if (TRANS) {
                    int f = kn + lq * 4;
                    v.x = fmaxf(v.x * g_stats[f + 0] + g_stats[128 + f + 0], 0.f);
                    v.y = fmaxf(v.y * g_stats[f + 1] + g_stats[128 + f + 1], 0.f);
                    v.z = fmaxf(v.z * g_stats[f + 2] + g_stats[128 + f + 2], 0.f);
                    v.w = fmaxf(v.w * g_stats[f + 3] + g_stats[128 + f + 3], 0.f);
                }
                pa[i] = v;
                pw[i] = *(const float4*)&W[(size_t)(kn + lk + i * 8) * 128 + lc * 4];
            }
        }
        #pragma unroll
        for (int k = 0; k < BK; k++) {
            float4 a0 = *(const float4*)&sA[k][ty * 8];
            float4 a1 = *(const float4*)&sA[k][ty * 8 + 4];
            float4 b0 = *(const float4*)&sW[k][tx * 8];
            float4 b1 = *(const float4*)&sW[k][tx * 8 + 4];
            unsigned long long bp[4] = {pk2(b0.x, b0.y), pk2(b0.z, b0.w),
                                        pk2(b1.x, b1.y), pk2(b1.z, b1.w)};
            float ar[8] = {a0.x, a0.y, a0.z, a0.w, a1.x, a1.y, a1.z, a1.w};
            #pragma unroll
            for (int r = 0; r < 8; r++) {
                unsigned long long ap = pk2(ar[r], ar[r]);
                ffma2(acc[r][0], ap, bp[0]);
                ffma2(acc[r][1], ap, bp[1]);
                ffma2(acc[r][2], ap, bp[2]);
                ffma2(acc[r][3], ap, bp[3]);
            }
        }
    }

    // columns tx*8..tx*8+7 (within one head); fp16 store + fused al
    float asr[8], adr[8];
    #pragma unroll
    for (int c = 0; c < 8; c++) {
        asr[c] = asrc[tx * 8 + c];
        adr[c] = adst[tx * 8 + c];
    }
    int head = tx >> 3;

    #pragma unroll
    for (int r = 0; r < 8; r++) {
        int gr = row0 + ty * 8 + r;
        float2 p0 = upk2(acc[r][0]), p1 = upk2(acc[r][1]);
        float2 p2 = upk2(acc[r][2]), p3 = upk2(acc[r][3]);
        float vr[8] = {p0.x, p0.y, p1.x, p1.y, p2.x, p2.y, p3.x, p3.y};
        if (gr < n) {
            __half2 hh[4];
            hh[0] = __floats2half2_rn(vr[0], vr[1]);
            hh[1] = __floats2half2_rn(vr[2], vr[3]);
            hh[2] = __floats2half2_rn(vr[4], vr[5]);
            hh[3] = __floats2half2_rn(vr[6], vr[7]);
            *(uint4*)&C[(size_t)gr * 64 + tx * 4] = *(uint4*)hh;
        }
        float s = 0.f, d = 0.f;
        #pragma unroll
        for (int c = 0; c < 8; c++) {
            s += vr[c] * asr[c];
            d += vr[c] * adr[c];
        }
        #pragma unroll
        for (int o = 1; o < 8; o <<= 1) {
            s += __shfl_xor_sync(0xffffffffu, s, o);
            d += __shfl_xor_sync(0xffffffffu, d, o);
        }
        if ((tx & 7) == 0 && gr < n) {
            g_als[gr * 2 + head] = s;
            g_ald[gr * 2 + head] = d;
        }
    }
}

// ---------------- small GEMM (layer 2, NC=40): BN+ReLU in, fp16 out, al ----
__global__ __launch_bounds__(256)
void gemm40_kernel(const float* __restrict__ A, const float* __restrict__ W,
                   __half* __restrict__ C,
                   const float* __restrict__ asrc, const float* __restrict__ adst,
                   int n) {
    constexpr int BM = 64, BK = 32, K = 128, NC = 40, NCPAD = 64;
    constexpr int CPT = NCPAD / 16;
    __shared__ float sA[BM][BK + 1];
    __shared__ float sW[BK][NCPAD];

    int tid = threadIdx.x;
    int tx = tid & 15, ty = tid >> 4;
    int row0 = blockIdx.x * BM;

    float acc[4][CPT];
    #pragma unroll
    for (int r = 0; r < 4; r++)
        #pragma unroll
        for (int c = 0; c < CPT; c++) acc[r][c] = 0.f;

    for (int k0 = 0; k0 < K; k0 += BK) {
        #pragma unroll
        for (int i = 0; i < (BM * BK) / 256; i++) {
            int e = tid + i * 256;
            int r = e >> 5, c = e & 31;
            int gr = row0 + r;
            float v = (gr < n) ? A[(size_t)gr * K + k0 + c] : 0.f;
            int f = k0 + c;
            v = fmaxf(v * g_stats[f] + g_stats[128 + f], 0.f);
            sA[r][c] = v;
        }
        #pragma unroll
        for (int i = 0; i < (BK * NCPAD) / 256; i++) {
            int e = tid + i * 256;
            int kk = e / NCPAD, c = e % NCPAD;
            sW[kk][c] = (c < NC) ? W[(size_t)(k0 + kk) * NC + c] : 0.f;
        }
        __syncthreads();
        #pragma unroll
        for (int k = 0; k < BK; k++) {
            float a0 = sA[ty * 4 + 0][k];
            float a1 = sA[ty * 4 + 1][k];
            float a2 = sA[ty * 4 + 2][k];
            float a3 = sA[ty * 4 + 3][k];
            #pragma unroll
            for (int c = 0; c < CPT; c++) {
                float w = sW[k][tx + c * 16];
                acc[0][c] += a0 * w;
                acc[1][c] += a1 * w;
                acc[2][c] += a2 * w;
                acc[3][c] += a3 * w;
            }
        }
        __syncthreads();
    }
    float asr[CPT], adr[CPT];
    #pragma unroll
    for (int c = 0; c < CPT; c++) {
        int col = tx + c * 16;
        asr[c] = (col < NC) ? asrc[col] : 0.f;
        adr[c] = (col < NC) ? adst[col] : 0.f;
    }
    #pragma unroll
    for (int r = 0; r < 4; r++) {
        int gr = row0 + ty * 4 + r;
        float s = 0.f, d = 0.f;
        #pragma unroll
        for (int c = 0; c < CPT; c++) {
            int col = tx + c * 16;
            if (gr < n && col < NC) C[(size_t)gr * NC + col] = __float2half_rn(acc[r][c]);
            s += acc[r][c] * asr[c];
            d += acc[r][c] * adr[c];
        }
        #pragma unroll
        for (int o = 1; o < 16; o <<= 1) {
            s += __shfl_xor_sync(0xffffffffu, s, o);
            d += __shfl_xor_sync(0xffffffffu, d, o);
        }
        if (tx == 0 && gr < n) {
            g_als[gr] = s;
            g_ald[gr] = d;
        }
    }
}

// ---------------- gather, H=2: pipelined batches, fp16 h -------------------
__global__ __launch_bounds__(512)
void gather2_kernel(const __half2* __restrict__ hin,
                    const float* __restrict__ bias,
                    float* __restrict__ out) {
    int gw = (blockIdx.x * blockDim.x + threadIdx.x) >> 5;
    int lane = threadIdx.x & 31;
    if (gw >= NN) return;
    int rs = g_rowptr[gw];
    int deg = g_rowptr[gw + 1] - rs;
    int head = lane >> 4;
    int sub = lane & 15;
    int hsel = head << 4;
    int col2 = lane * 2;

    if (deg == 0) {
        *(float4*)&out[(size_t)gw * 128 + lane * 4] = *(const float4*)&bias[lane * 4];
        return;
    }
    const float* ewp = head ? g_ew1 : g_ew0;

    float4 acc = make_float4(0.f, 0.f, 0.f, 0.f);
    float sum = 0.f;

    // software-pipelined batches of 16 edges
    int p0 = sub;
    bool v0 = p0 < deg;
    int sj = v0 ? g_perm_src[rs + p0] : 0;
    float e = v0 ? ewp[rs + p0] : 0.f;

    for (int base = 0; base < deg; base += 16) {
        // prefetch next batch's index + weight
        int pn = base + 16 + sub;
        bool vn = pn < deg;
        int sjn = vn ? g_perm_src[rs + pn] : 0;
        float en = vn ? ewp[rs + pn] : 0.f;

        #pragma unroll
        for (int j = 0; j < 16; j++) {
            float w = __shfl_sync(0xffffffffu, e, hsel | j);
            int s = __shfl_sync(0xffffffffu, sj, j);
            sum += w;
            uint2 hv = *(const uint2*)&hin[(size_t)s * 64 + col2];
            float2 f0 = __half22float2(*(const __half2*)&hv.x);
            float2 f1 = __half22float2(*(const __half2*)&hv.y);
            acc.x += w * f0.x;
            acc.y += w * f0.y;
            acc.z += w * f1.x;
            acc.w += w * f1.y;
        }
        sj = sjn;
        e = en;
    }
    float idn = 1.f / (sum + 1e-16f);
    float4 b4 = *(const float4*)&bias[lane * 4];
    float4 o;
    o.x = acc.x * idn + b4.x;
    o.y = acc.y * idn + b4.y;
    o.z = acc.z * idn + b4.z;
    o.w = acc.w * idn + b4.w;
    *(float4*)&out[(size_t)gw * 128 + lane * 4] = o;
}

// ---------------- gather, H=1 (layer 2): 40 cols, fp16 h -------------------
__global__ __launch_bounds__(512)
void gather1_kernel(const __half* __restrict__ hin,
                    const float* __restrict__ bias,
                    float* __restrict__ out) {
    constexpr int F = 40;
    constexpr int NV = 10;
    int gw = (blockIdx.x * blockDim.x + threadIdx.x) >> 5;
    int lane = threadIdx.x & 31;
    if (gw >= NN) return;
    int rs = g_rowptr[gw];
    int deg = g_rowptr[gw + 1] - rs;
    bool act = lane < NV;
    int col = lane * 4;

    if (deg == 0) {
        if (act) *(float4*)&out[(size_t)gw * F + col] = *(const float4*)&bias[col];
        return;
    }

    float4 acc = make_float4(0.f, 0.f, 0.f, 0.f);
    float sum = 0.f;
    const __half2* h2 = (const __half2*)hin;

    int p0 = lane;
    bool v0 = p0 < deg;
    int sj = v0 ? g_perm_src[rs + p0] : 0;
    float e = v0 ? g_ew0[rs + p0] : 0.f;

    for (int base = 0; base < deg; base += 32) {
        int pn = base + 32 + lane;
        bool vn = pn < deg;
        int sjn = vn ? g_perm_src[rs + pn] : 0;
        float en = vn ? g_ew0[rs + pn] : 0.f;

        #pragma unroll
        for (int j = 0; j < 32; j++) {
            float w = __shfl_sync(0xffffffffu, e, j);
            int s = __shfl_sync(0xffffffffu, sj, j);
            sum += w;
            if (act) {
                uint2 hv = *(const uint2*)&h2[(size_t)s * 20 + lane * 2];
                float2 f0 = __half22float2(*(const __half2*)&hv.x);
                float2 f1 = __half22float2(*(const __half2*)&hv.y);
                acc.x += w * f0.x;
                acc.y += w * f0.y;
                acc.z += w * f1.x;
                acc.w += w * f1.y;
            }
        }
        sj = sjn;
        e = en;
    }
    if (act) {
        float idn = 1.f / (sum + 1e-16f);
        float4 b4 = *(const float4*)&bias[col];
        float4 o;
        o.x = acc.x * idn + b4.x;
        o.y = acc.y * idn + b4.y;
        o.z = acc.z * idn + b4.z;
        o.w = acc.w * idn + b4.w;
        *(float4*)&out[(size_t)gw * F + col] = o;
    }
}

// ---------------- batch norm (accumulators zeroed in k_init) ---------------
__global__ void bn_accum(const float* __restrict__ h, float* __restrict__ acc, int n) {
    int f = threadIdx.x;  // 128
    float s = 0.f, s2 = 0.f;
    for (int r = blockIdx.x; r < n; r += gridDim.x) {
        float v = h[(size_t)r * 128 + f];
        s += v;
        s2 += v * v;
    }
    atomicAdd(&acc[f], s);
    atomicAdd(&acc[128 + f], s2);
}

__global__ void bn_final(const float* __restrict__ acc,
                         const float* __restrict__ g,
                         const float* __restrict__ beta, float inv_n) {
    int f = threadIdx.x;  // 128
    float mu = acc[f] * inv_n;
    float var = acc[128 + f] * inv_n - mu * mu;
    float sc = rsqrtf(var + BN_EPS) * g[f];
    float sh = beta[f] - mu * sc;
    g_stats[f] = sc;
    g_stats[128 + f] = sh;
}

// ---------------- launch ---------------------------------------------------
extern "C" void kernel_launch(void* const* d_in, const int* in_sizes, int n_in,
                              void* d_out, int out_size) {
    const float* x     = (const float*)d_in[0];
    const int*   eiw   = (const int*)d_in[1];
    const float* w0    = (const float*)d_in[2];
    const float* asrc0 = (const float*)d_in[3];
    const float* adst0 = (const float*)d_in[4];
    const float* b0    = (const float*)d_in[5];
    const float* gg0   = (const float*)d_in[6];
    const float* beta0 = (const float*)d_in[7];
    const float* w1    = (const float*)d_in[8];
    const float* asrc1 = (const float*)d_in[9];
    const float* adst1 = (const float*)d_in[10];
    const float* b1    = (const float*)d_in[11];
    const float* gg1   = (const float*)d_in[12];
    const float* beta1 = (const float*)d_in[13];
    const float* w2    = (const float*)d_in[14];
    const float* asrc2 = (const float*)d_in[15];
    const float* adst2 = (const float*)d_in[16];
    const float* b2    = (const float*)d_in[17];
    float* out = (float*)d_out;

    __half2* h16 = nullptr;
    float *bufB = nullptr, *acc0 = nullptr, *acc1 = nullptr;
    cudaGetSymbolAddress((void**)&h16, g_h16);
    cudaGetSymbolAddress((void**)&bufB, g_bufB);
    cudaGetSymbolAddress((void**)&acc0, g_acc0);
    cudaGetSymbolAddress((void**)&acc1, g_acc1);

    static cudaStream_t s2 = nullptr;
    static cudaEvent_t evFork = nullptr, evJoin = nullptr;
    if (s2 == nullptr) {
        cudaStreamCreateWithFlags(&s2, cudaStreamNonBlocking);
        cudaEventCreateWithFlags(&evFork, cudaEventDisableTiming);
        cudaEventCreateWithFlags(&evJoin, cudaEventDisableTiming);
    }

    const int nb = (NN + 1023) / 1024;
    const int gE4 = (EE / 4 + 255) / 256;
    const int gN = (NN + 255) / 256;
    const int gW = (NN * 32 + 511) / 512;
    const int gM128 = (NN + 127) / 128;
    const int gM64 = (NN + 63) / 64;

    // ---- fork: CSR prefix on s2, gemm L0 interleaved at submission idx 3 ---
    cudaEventRecord(evFork, 0);
    cudaStreamWaitEvent(s2, evFork, 0);
    k_init<<<gN, 256, 0, s2>>>(eiw);                              // 0
    k_count<<<gE4, 256, 0, s2>>>(eiw);                            // 1
    k_scan1<<<nb, 1024, 0, s2>>>();                               // 2
    gemm128_kernel<false><<<gM128, 256>>>(x, w0, h16, asrc0, adst0, NN);  // 3 (profiled)
    k_scan23<<<gN, 256, 0, s2>>>(nb);                             // 4
    k_scatter<<<gE4, 256, 0, s2>>>(eiw);                          // 5
    cudaEventRecord(evJoin, s2);
    cudaStreamWaitEvent(0, evJoin, 0);

    const float inv_n = 1.0f / (float)NN;

    // ---- layer 0 tail ----
    ew2_kernel<<<gE4, 256>>>();
    gather2_kernel<<<gW, 512>>>(h16, b0, bufB);
    bn_accum<<<512, 128>>>(bufB, acc0, NN);
    bn_final<<<1, 128>>>(acc0, gg0, beta0, inv_n);

    // ---- layer 1 ----
    gemm128_kernel<true><<<gM128, 256>>>(bufB, w1, h16, asrc1, adst1, NN);
    ew2_kernel<<<gE4, 256>>>();
    gather2_kernel<<<gW, 512>>>(h16, b1, bufB);
    bn_accum<<<512, 128>>>(bufB, acc1, NN);
    bn_final<<<1, 128>>>(acc1, gg1, beta1, inv_n);

    // ---- layer 2 ----
    gemm40_kernel<<<gM64, 256>>>(bufB, w2, (__half*)h16, asrc2, adst2, NN);
    ew1_kernel<<<gE4, 256>>>();
    gather1_kernel<<<gW, 512>>>((const __half*)h16, b2, out);
}

// round 12
// speedup vs baseline: 1.0955x; 1.0955x over previous
#include <cuda_runtime.h>
#include <cuda_fp16.h>
#include <math.h>

// Problem constants (fixed by the reference)
#define NN   100000
#define EE   1600000
#define BN_EPS 1e-5f
#define SLOPE 0.2f

// ---------------- scratch (device globals; no allocation allowed) ----------
__device__ __half2 g_h16[(size_t)NN * 64];   // h in fp16 (128 halfs/row; L2: 40)
__device__ float  g_bufB[(size_t)NN * 128];  // gather output (fp32, BN input)
__device__ float  g_als[NN * 2];
__device__ float  g_ald[NN * 2];
__device__ float  g_ew0[EE];                 // per-edge exp weights, head 0
__device__ float  g_ew1[EE];                 // head 1
__device__ int    g_deg[NN];
__device__ int    g_rowptr[NN + 1];
__device__ int    g_cursor[NN];
__device__ int    g_perm_src[EE];
__device__ int    g_perm_dst[EE];
__device__ int    g_bsum[128];
__device__ int    g_is64;
__device__ float  g_acc0[256];               // BN accum layer 0 (zeroed in init)
__device__ float  g_acc1[256];               // BN accum layer 1
__device__ float  g_stats[256];  // [0:128) scale, [128:256) shift (current)

// ---------------- mma.sync m16n8k16 fp16 -> fp32 ---------------------------
__device__ __forceinline__ void mma16816(float* c,
                                         unsigned a0, unsigned a1, unsigned a2, unsigned a3,
                                         unsigned b0, unsigned b1) {
    asm("mma.sync.aligned.m16n8k16.row.col.f32.f16.f16.f32 "
        "{%0,%1,%2,%3}, {%4,%5,%6,%7}, {%8,%9}, {%0,%1,%2,%3};\n"
        : "+f"(c[0]), "+f"(c[1]), "+f"(c[2]), "+f"(c[3])
        : "r"(a0), "r"(a1), "r"(a2), "r"(a3), "r"(b0), "r"(b1));
}

// ---------------- init: dtype detect + zero deg + zero BN accumulators -----
__global__ void k_init(const int* __restrict__ w) {
    int i = blockIdx.x * blockDim.x + threadIdx.x;
    if (i < NN) g_deg[i] = 0;
    if (blockIdx.x == 0) {
        __shared__ int nz;
        if (threadIdx.x == 0) nz = 0;
        if (threadIdx.x < 256) {
            g_acc0[threadIdx.x] = 0.f;
            g_acc1[threadIdx.x] = 0.f;
        }
        __syncthreads();
        for (int j = threadIdx.x; j < 1024; j += blockDim.x)
            if (w[2 * j + 1] != 0) nz = 1;
        __syncthreads();
        if (threadIdx.x == 0) g_is64 = nz ? 0 : 1;
    }
}

// ---------------- CSR build ------------------------------------------------
__global__ void k_count(const int* __restrict__ w) {
    int t = blockIdx.x * blockDim.x + threadIdx.x;
    int base = t * 4;
    int is64 = g_is64;
    #pragma unroll
    for (int i = 0; i < 4; i++) {
        int e = base + i;
        if (e < EE) {
            int d = is64 ? w[2 * EE + 2 * e] : w[EE + e];
            if ((unsigned)d >= NN) d = 0;
            atomicAdd(&g_deg[d], 1);
        }
    }
}

__global__ void k_scan1() {
    __shared__ int sh[1024];
    int t = threadIdx.x;
    int i = blockIdx.x * 1024 + t;
    int v = (i < NN) ? g_deg[i] : 0;
    sh[t] = v;
    __syncthreads();
    #pragma unroll
    for (int off = 1; off < 1024; off <<= 1) {
        int x = (t >= off) ? sh[t - off] : 0;
        __syncthreads();
        sh[t] += x;
        __syncthreads();
    }
    if (i < NN) g_rowptr[i] = sh[t] - v;
    if (t == 1023) g_bsum[blockIdx.x] = sh[t];
}

__global__ void k_scan23(int nb) {
    __shared__ int pre[128];
    __shared__ int total;
    int t = threadIdx.x;
    if (t < nb) pre[t] = g_bsum[t];
    __syncthreads();
    if (t == 0) {
        int run = 0;
        for (int b = 0; b < nb; b++) {
            int x = pre[b];
            pre[b] = run;
            run += x;
        }
        total = run;
    }
    __syncthreads();
    int i = blockIdx.x * blockDim.x + t;
    if (i < NN) {
        int v = g_rowptr[i] + pre[i >> 10];
        g_rowptr[i] = v;
        g_cursor[i] = v;
    }
    if (i == 0) g_rowptr[NN] = total;
}

__global__ void k_scatter(const int* __restrict__ w) {
    int t = blockIdx.x * blockDim.x + threadIdx.x;
    int base = t * 4;
    int is64 = g_is64;
    #pragma unroll
    for (int i = 0; i < 4; i++) {
        int e = base + i;
        if (e < EE) {
            int s, d;
            if (is64) {
                s = w[2 * e];
                d = w[2 * EE + 2 * e];
            } else {
                s = w[e];
                d = w[EE + e];
            }
            if ((unsigned)s >= NN) s = 0;
            if ((unsigned)d >= NN) d = 0;
            int pos = atomicAdd(&g_cursor[d], 1);
            g_perm_src[pos] = s;
            g_perm_dst[pos] = d;
        }
    }
}

// ---------------- edge weights: ew = exp(leaky(als[src] + ald[dst])) -------
__global__ void ew2_kernel() {
    int t = blockIdx.x * blockDim.x + threadIdx.x;
    int base = t * 4;
    #pragma unroll
    for (int i = 0; i < 4; i++) {
        int p = base + i;
        if (p < EE) {
            int s = g_perm_src[p];
            int d = g_perm_dst[p];
            float2 as = *(const float2*)&g_als[s * 2];
            float2 ad = *(const float2*)&g_ald[d * 2];
            float v0 = as.x + ad.x; v0 = v0 > 0.f ? v0 : SLOPE * v0;
            float v1 = as.y + ad.y; v1 = v1 > 0.f ? v1 : SLOPE * v1;
            g_ew0[p] = __expf(v0);
            g_ew1[p] = __expf(v1);
        }
    }
}

__global__ void ew1_kernel() {
    int t = blockIdx.x * blockDim.x + threadIdx.x;
    int base = t * 4;
    #pragma unroll
    for (int i = 0; i < 4; i++) {
        int p = base + i;
        if (p < EE) {
            int s = g_perm_src[p];
            int d = g_perm_dst[p];
            float v0 = g_als[s] + g_ald[d];
            v0 = v0 > 0.f ? v0 : SLOPE * v0;
            g_ew0[p] = __expf(v0);
        }
    }
}

// ---------------- tensor-core GEMM 128x128: HMMA, BN+ReLU in, fp16 out, al -
// Block 256 thr (8 warps). Warp w owns rows [w*16, w*16+16) x all 128 cols.
// K processed in two 64-wide phases; A and W^T staged in fp16 smem.
template <bool TRANS>
__global__ __launch_bounds__(256)
void gemm128_tc(const float* __restrict__ A, const float* __restrict__ W,
                __half2* __restrict__ C,
                const float* __restrict__ asrc, const float* __restrict__ adst,
                int n) {
    __shared__ __half sA[128 * 72];   // [row][k] stride 72 halfs
    __shared__ __half sB[128 * 72];   // [n][k]  stride 72 halfs (W transposed)

    int tid = threadIdx.x;
    int lane = tid & 31, wid = tid >> 5;
    int g = lane >> 2, tig = lane & 3;
    int row0 = blockIdx.x * 128;

    float c[16][4];
    #pragma unroll
    for (int t = 0; t < 16; t++)
        #pragma unroll
        for (int j = 0; j < 4; j++) c[t][j] = 0.f;

    #pragma unroll
    for (int p = 0; p < 2; p++) {
        int k0 = p * 64;
        __syncthreads();
        // stage A (fp32 -> fp16, optional BN+ReLU)
        #pragma unroll
        for (int i = 0; i < 8; i++) {
            int idx = tid + i * 256;        // 0..2047
            int r = idx >> 4;
            int q = idx & 15;               // float4 within the 64-k phase
            int gr = row0 + r;
            float4 v = make_float4(0.f, 0.f, 0.f, 0.f);
            if (gr < n) v = *(const float4*)&A[(size_t)gr * 128 + k0 + q * 4];
            if (TRANS) {
                int f = k0 + q * 4;
                v.x = fmaxf(v.x * g_stats[f + 0] + g_stats[128 + f + 0], 0.f);
                v.y = fmaxf(v.y * g_stats[f + 1] + g_stats[128 + f + 1], 0.f);
                v.z = fmaxf(v.z * g_stats[f + 2] + g_stats[128 + f + 2], 0.f);
                v.w = fmaxf(v.w * g_stats[f + 3] + g_stats[128 + f + 3], 0.f);
            }
            *(__half2*)&sA[r * 72 + q * 4] = __floats2half2_rn(v.x, v.y);
            *(__half2*)&sA[r * 72 + q * 4 + 2] = __floats2half2_rn(v.z, v.w);
        }
        // stage W^T (fp32 -> fp16)
        #pragma unroll
        for (int i = 0; i < 8; i++) {
            int idx = tid + i * 256;
            int kk = idx >> 5;              // 0..63
            int nq = idx & 31;
            float4 v = *(const float4*)&W[(size_t)(k0 + kk) * 128 + nq * 4];
            sB[(nq * 4 + 0) * 72 + kk] = __float2half_rn(v.x);
            sB[(nq * 4 + 1) * 72 + kk] = __float2half_rn(v.y);
            sB[(nq * 4 + 2) * 72 + kk] = __float2half_rn(v.z);
            sB[(nq * 4 + 3) * 72 + kk] = __float2half_rn(v.w);
        }
        __syncthreads();
        // compute: 4 k-chunks of 16
        const __half* pa = &sA[(wid * 16 + g) * 72];
        #pragma unroll
        for (int kc = 0; kc < 4; kc++) {
            int kb = kc * 16 + 2 * tig;
            unsigned a0 = *(const unsigned*)&pa[kb];
            unsigned a1 = *(const unsigned*)&pa[8 * 72 + kb];
            unsigned a2 = *(const unsigned*)&pa[kb + 8];
            unsigned a3 = *(const unsigned*)&pa[8 * 72 + kb + 8];
            #pragma unroll
            for (int t = 0; t < 16; t++) {
                const __half* pb = &sB[(t * 8 + g) * 72 + kb];
                unsigned b0 = *(const unsigned*)&pb[0];
                unsigned b1 = *(const unsigned*)&pb[8];
                mma16816(c[t], a0, a1, a2, a3, b0, b1);
            }
        }
    }

    // epilogue: fp16 store + fused attention logits
    int r0 = row0 + wid * 16 + g;       // rows for c0,c1
    int r1 = r0 + 8;                    // rows for c2,c3
    float sh0[2] = {0.f, 0.f}, dh0[2] = {0.f, 0.f};   // row r0, per head
    float sh1[2] = {0.f, 0.f}, dh1[2] = {0.f, 0.f};   // row r1, per head
    bool v0 = r0 < n, v1 = r1 < n;

    #pragma unroll
    for (int t = 0; t < 16; t++) {
        int col = t * 8 + 2 * tig;
        float as0 = asrc[col], as1 = asrc[col + 1];
        float ad0 = adst[col], ad1 = adst[col + 1];
        int hd = t >> 3;
        sh0[hd] += c[t][0] * as0 + c[t][1] * as1;
        dh0[hd] += c[t][0] * ad0 + c[t][1] * ad1;
        sh1[hd] += c[t][2] * as0 + c[t][3] * as1;
        dh1[hd] += c[t][2] * ad0 + c[t][3] * ad1;
        if (v0) C[(size_t)r0 * 64 + t * 4 + tig] = __floats2half2_rn(c[t][0], c[t][1]);
        if (v1) C[(size_t)r1 * 64 + t * 4 + tig] = __floats2half2_rn(c[t][2], c[t][3]);
    }
    // reduce over the 4 lanes (tig) of this group
    #pragma unroll
    for (int o = 1; o < 4; o <<= 1) {
        #pragma unroll
        for (int hd = 0; hd < 2; hd++) {
            sh0[hd] += __shfl_xor_sync(0xffffffffu, sh0[hd], o);
            dh0[hd] += __shfl_xor_sync(0xffffffffu, dh0[hd], o);
            sh1[hd] += __shfl_xor_sync(0xffffffffu, sh1[hd], o);
            dh1[hd] += __shfl_xor_sync(0xffffffffu, dh1[hd], o);
        }
    }
    if (tig == 0) {
        #pragma unroll
        for (int hd = 0; hd < 2; hd++) {
            if (v0) { g_als[r0 * 2 + hd] = sh0[hd]; g_ald[r0 * 2 + hd] = dh0[hd]; }
            if (v1) { g_als[r1 * 2 + hd] = sh1[hd]; g_ald[r1 * 2 + hd] = dh1[hd]; }
        }
    }
}

// ---------------- small GEMM (layer 2, NC=40): BN+ReLU in, fp16 out, al ----
__global__ __launch_bounds__(256)
void gemm40_kernel(const float* __restrict__ A, const float* __restrict__ W,
                   __half* __restrict__ C,
                   const float* __restrict__ asrc, const float* __restrict__ adst,
                   int n) {
    constexpr int BM = 64, BK = 32, K = 128, NC = 40, NCPAD = 64;
    constexpr int CPT = NCPAD / 16;
    __shared__ float sA[BM][BK + 1];
    __shared__ float sW[BK][NCPAD];

    int tid = threadIdx.x;
    int tx = tid & 15, ty = tid >> 4;
    int row0 = blockIdx.x * BM;

    float acc[4][CPT];
    #pragma unroll
    for (int r = 0; r < 4; r++)
        #pragma unroll
        for (int c = 0; c < CPT; c++) acc[r][c] = 0.f;

    for (int k0 = 0; k0 < K; k0 += BK) {
        #pragma unroll
        for (int i = 0; i < (BM * BK) / 256; i++) {
            int e = tid + i * 256;
            int r = e >> 5, c = e & 31;
            int gr = row0 + r;
            float v = (gr < n) ? A[(size_t)gr * K + k0 + c] : 0.f;
            int f = k0 + c;
            v = fmaxf(v * g_stats[f] + g_stats[128 + f], 0.f);
            sA[r][c] = v;
        }
        #pragma unroll
        for (int i = 0; i < (BK * NCPAD) / 256; i++) {
            int e = tid + i * 256;
            int kk = e / NCPAD, c = e % NCPAD;
            sW[kk][c] = (c < NC) ? W[(size_t)(k0 + kk) * NC + c] : 0.f;
        }
        __syncthreads();
        #pragma unroll
        for (int k = 0; k < BK; k++) {
            float a0 = sA[ty * 4 + 0][k];
            float a1 = sA[ty * 4 + 1][k];
            float a2 = sA[ty * 4 + 2][k];
            float a3 = sA[ty * 4 + 3][k];
            #pragma unroll
            for (int c = 0; c < CPT; c++) {
                float w = sW[k][tx + c * 16];
                acc[0][c] += a0 * w;
                acc[1][c] += a1 * w;
                acc[2][c] += a2 * w;
                acc[3][c] += a3 * w;
            }
        }
        __syncthreads();
    }
    float asr[CPT], adr[CPT];
    #pragma unroll
    for (int c = 0; c < CPT; c++) {
        int col = tx + c * 16;
        asr[c] = (col < NC) ? asrc[col] : 0.f;
        adr[c] = (col < NC) ? adst[col] : 0.f;
    }
    #pragma unroll
    for (int r = 0; r < 4; r++) {
        int gr = row0 + ty * 4 + r;
        float s = 0.f, d = 0.f;
        #pragma unroll
        for (int c = 0; c < CPT; c++) {
            int col = tx + c * 16;
            if (gr < n && col < NC) C[(size_t)gr * NC + col] = __float2half_rn(acc[r][c]);
            s += acc[r][c] * asr[c];
            d += acc[r][c] * adr[c];
        }
        #pragma unroll
        for (int o = 1; o < 16; o <<= 1) {
            s += __shfl_xor_sync(0xffffffffu, s, o);
            d += __shfl_xor_sync(0xffffffffu, d, o);
        }
        if (tx == 0 && gr < n) {
            g_als[gr] = s;
            g_ald[gr] = d;
        }
    }
}

// ---------------- gather, H=2: pipelined 16-edge batches, fp16 h -----------
__global__ __launch_bounds__(256)
void gather2_kernel(const __half2* __restrict__ hin,
                    const float* __restrict__ bias,
                    float* __restrict__ out) {
    int gw = (blockIdx.x * blockDim.x + threadIdx.x) >> 5;
    int lane = threadIdx.x & 31;
    if (gw >= NN) return;
    int rs = g_rowptr[gw];
    int deg = g_rowptr[gw + 1] - rs;
    int head = lane >> 4;
    int sub = lane & 15;
    int hsel = head << 4;
    int col2 = lane * 2;

    if (deg == 0) {
        *(float4*)&out[(size_t)gw * 128 + lane * 4] = *(const float4*)&bias[lane * 4];
        return;
    }
    const float* ewp = head ? g_ew1 : g_ew0;

    float4 acc = make_float4(0.f, 0.f, 0.f, 0.f);
    float sum = 0.f;

    int p0 = sub;
    bool vv = p0 < deg;
    int sj = vv ? g_perm_src[rs + p0] : 0;
    float e = vv ? ewp[rs + p0] : 0.f;

    for (int base = 0; base < deg; base += 16) {
        int pn = base + 16 + sub;
        bool vn = pn < deg;
        int sjn = vn ? g_perm_src[rs + pn] : 0;
        float en = vn ? ewp[rs + pn] : 0.f;

        #pragma unroll
        for (int j = 0; j < 16; j++) {
            float w = __shfl_sync(0xffffffffu, e, hsel | j);
            int s = __shfl_sync(0xffffffffu, sj, j);
            sum += w;
            uint2 hv = *(const uint2*)&hin[(size_t)s * 64 + col2];
            float2 f0 = __half22float2(*(const __half2*)&hv.x);
            float2 f1 = __half22float2(*(const __half2*)&hv.y);
            acc.x += w * f0.x;
            acc.y += w * f0.y;
            acc.z += w * f1.x;
            acc.w += w * f1.y;
        }
        sj = sjn;
        e = en;
    }
    float idn = 1.f / (sum + 1e-16f);
    float4 b4 = *(const float4*)&bias[lane * 4];
    float4 o;
    o.x = acc.x * idn + b4.x;
    o.y = acc.y * idn + b4.y;
    o.z = acc.z * idn + b4.z;
    o.w = acc.w * idn + b4.w;
    *(float4*)&out[(size_t)gw * 128 + lane * 4] = o;
}

// ---------------- gather, H=1 (layer 2): 40 cols, fp16 h -------------------
__global__ __launch_bounds__(256)
void gather1_kernel(const __half* __restrict__ hin,
                    const float* __restrict__ bias,
                    float* __restrict__ out) {
    constexpr int F = 40;
    constexpr int NV = 10;
    int gw = (blockIdx.x * blockDim.x + threadIdx.x) >> 5;
    int lane = threadIdx.x & 31;
    if (gw >= NN) return;
    int rs = g_rowptr[gw];
    int deg = g_rowptr[gw + 1] - rs;
    bool act = lane < NV;
    int col = lane * 4;

    if (deg == 0) {
        if (act) *(float4*)&out[(size_t)gw * F + col] = *(const float4*)&bias[col];
        return;
    }

    float4 acc = make_float4(0.f, 0.f, 0.f, 0.f);
    float sum = 0.f;
    const __half2* h2 = (const __half2*)hin;

    int p0 = lane;
    bool vv = p0 < deg;
    int sj = vv ? g_perm_src[rs + p0] : 0;
    float e = vv ? g_ew0[rs + p0] : 0.f;

    for (int base = 0; base < deg; base += 32) {
        int pn = base + 32 + lane;
        bool vn = pn < deg;
        int sjn = vn ? g_perm_src[rs + pn] : 0;
        float en = vn ? g_ew0[rs + pn] : 0.f;

        #pragma unroll
        for (int j = 0; j < 32; j++) {
            float w = __shfl_sync(0xffffffffu, e, j);
            int s = __shfl_sync(0xffffffffu, sj, j);
            sum += w;
            if (act) {
                uint2 hv = *(const uint2*)&h2[(size_t)s * 20 + lane * 2];
                float2 f0 = __half22float2(*(const __half2*)&hv.x);
                float2 f1 = __half22float2(*(const __half2*)&hv.y);
                acc.x += w * f0.x;
                acc.y += w * f0.y;
                acc.z += w * f1.x;
                acc.w += w * f1.y;
            }
        }
        sj = sjn;
        e = en;
    }
    if (act) {
        float idn = 1.f / (sum + 1e-16f);
        float4 b4 = *(const float4*)&bias[col];
        float4 o;
        o.x = acc.x * idn + b4.x;
        o.y = acc.y * idn + b4.y;
        o.z = acc.z * idn + b4.z;
        o.w = acc.w * idn + b4.w;
        *(float4*)&out[(size_t)gw * F + col] = o;
    }
}

// ---------------- batch norm (accumulators zeroed in k_init) ---------------
__global__ void bn_accum(const float* __restrict__ h, float* __restrict__ acc, int n) {
    int f = threadIdx.x;  // 128
    float s = 0.f, s2 = 0.f;
    for (int r = blockIdx.x; r < n; r += gridDim.x) {
        float v = h[(size_t)r * 128 + f];
        s += v;
        s2 += v * v;
    }
    atomicAdd(&acc[f], s);
    atomicAdd(&acc[128 + f], s2);
}

__global__ void bn_final(const float* __restrict__ acc,
                         const float* __restrict__ g,
                         const float* __restrict__ beta, float inv_n) {
    int f = threadIdx.x;  // 128
    float mu = acc[f] * inv_n;
    float var = acc[128 + f] * inv_n - mu * mu;
    float sc = rsqrtf(var + BN_EPS) * g[f];
    float sh = beta[f] - mu * sc;
    g_stats[f] = sc;
    g_stats[128 + f] = sh;
}

// ---------------- launch ---------------------------------------------------
extern "C" void kernel_launch(void* const* d_in, const int* in_sizes, int n_in,
                              void* d_out, int out_size) {
    const float* x     = (const float*)d_in[0];
    const int*   eiw   = (const int*)d_in[1];
    const float* w0    = (const float*)d_in[2];
    const float* asrc0 = (const float*)d_in[3];
    const float* adst0 = (const float*)d_in[4];
    const float* b0    = (const float*)d_in[5];
    const float* gg0   = (const float*)d_in[6];
    const float* beta0 = (const float*)d_in[7];
    const float* w1    = (const float*)d_in[8];
    const float* asrc1 = (const float*)d_in[9];
    const float* adst1 = (const float*)d_in[10];
    const float* b1    = (const float*)d_in[11];
    const float* gg1   = (const float*)d_in[12];
    const float* beta1 = (const float*)d_in[13];
    const float* w2    = (const float*)d_in[14];
    const float* asrc2 = (const float*)d_in[15];
    const float* adst2 = (const float*)d_in[16];
    const float* b2    = (const float*)d_in[17];
    float* out = (float*)d_out;

    __half2* h16 = nullptr;
    float *bufB = nullptr, *acc0 = nullptr, *acc1 = nullptr;
    cudaGetSymbolAddress((void**)&h16, g_h16);
    cudaGetSymbolAddress((void**)&bufB, g_bufB);
    cudaGetSymbolAddress((void**)&acc0, g_acc0);
    cudaGetSymbolAddress((void**)&acc1, g_acc1);

    static cudaStream_t s2 = nullptr;
    static cudaEvent_t evFork = nullptr, evJoin = nullptr;
    if (s2 == nullptr) {
        cudaStreamCreateWithFlags(&s2, cudaStreamNonBlocking);
        cudaEventCreateWithFlags(&evFork, cudaEventDisableTiming);
        cudaEventCreateWithFlags(&evJoin, cudaEventDisableTiming);
    }

    const int nb = (NN + 1023) / 1024;
    const int gE4 = (EE / 4 + 255) / 256;
    const int gN = (NN + 255) / 256;
    const int gW = (NN * 32 + 255) / 256;
    const int gM128 = (NN + 127) / 128;
    const int gM64 = (NN + 63) / 64;

    // ---- fork: CSR prefix on s2, gemm L0 at submission idx 3 (profiled) ----
    cudaEventRecord(evFork, 0);
    cudaStreamWaitEvent(s2, evFork, 0);
    k_init<<<gN, 256, 0, s2>>>(eiw);                              // 0
    k_count<<<gE4, 256, 0, s2>>>(eiw);                            // 1
    k_scan1<<<nb, 1024, 0, s2>>>();                               // 2
    gemm128_tc<false><<<gM128, 256>>>(x, w0, h16, asrc0, adst0, NN);  // 3 (profiled)
    k_scan23<<<gN, 256, 0, s2>>>(nb);                             // 4
    k_scatter<<<gE4, 256, 0, s2>>>(eiw);                          // 5
    cudaEventRecord(evJoin, s2);
    cudaStreamWaitEvent(0, evJoin, 0);

    const float inv_n = 1.0f / (float)NN;

    // ---- layer 0 tail ----
    ew2_kernel<<<gE4, 256>>>();
    gather2_kernel<<<gW, 256>>>(h16, b0, bufB);
    bn_accum<<<512, 128>>>(bufB, acc0, NN);
    bn_final<<<1, 128>>>(acc0, gg0, beta0, inv_n);

    // ---- layer 1 ----
    gemm128_tc<true><<<gM128, 256>>>(bufB, w1, h16, asrc1, adst1, NN);
    ew2_kernel<<<gE4, 256>>>();
    gather2_kernel<<<gW, 256>>>(h16, b1, bufB);
    bn_accum<<<512, 128>>>(bufB, acc1, NN);
    bn_final<<<1, 128>>>(acc1, gg1, beta1, inv_n);

    // ---- layer 2 ----
    gemm40_kernel<<<gM64, 256>>>(bufB, w2, (__half*)h16, asrc2, adst2, NN);
    ew1_kernel<<<gE4, 256>>>();
    gather1_kernel<<<gW, 256>>>((const __half*)h16, b2, out);
}

// round 14
// speedup vs baseline: 1.2688x; 1.1582x over previous
#include <cuda_runtime.h>
#include <cuda_fp16.h>
#include <math.h>

#define NN   100000
#define EE   1600000
#define BN_EPS 1e-5f
#define SLOPE 0.2f

// ---------------- scratch (device globals; no allocation allowed) ----------
__device__ __half2 g_h16[(size_t)NN * 64];   // h in fp16 (128 halfs/row)
__device__ float  g_bufB[(size_t)NN * 128];  // gather output (fp32)
__device__ float  g_als[NN * 2];
__device__ float  g_ald[NN * 2];
__device__ float  g_ew0[EE];
__device__ float  g_ew1[EE];
__device__ __half g_wt0[128 * 128];          // W0^T fp16 [n][k]
__device__ __half g_wt1[128 * 128];          // W1^T fp16 [n][k]
__device__ int    g_deg[NN];
__device__ int    g_rowptr[NN + 1];
__device__ int    g_cursor[NN];
__device__ int    g_perm_src[EE];
__device__ int    g_perm_dst[EE];
__device__ int    g_bsum[128];
__device__ int    g_is64;
__device__ float  g_acc0[256];
__device__ float  g_acc1[256];
__device__ float  g_stats[256];

__device__ __forceinline__ unsigned smem_u32(const void* p) {
    return (unsigned)__cvta_generic_to_shared(p);
}

__device__ __forceinline__ void mma16816(float* c,
                                         unsigned a0, unsigned a1, unsigned a2, unsigned a3,
                                         unsigned b0, unsigned b1) {
    asm("mma.sync.aligned.m16n8k16.row.col.f32.f16.f16.f32 "
        "{%0,%1,%2,%3}, {%4,%5,%6,%7}, {%8,%9}, {%0,%1,%2,%3};\n"
        : "+f"(c[0]), "+f"(c[1]), "+f"(c[2]), "+f"(c[3])
        : "r"(a0), "r"(a1), "r"(a2), "r"(a3), "r"(b0), "r"(b1));
}

__device__ __forceinline__ void ldsm4(unsigned& r0, unsigned& r1, unsigned& r2, unsigned& r3,
                                      unsigned addr) {
    asm volatile("ldmatrix.sync.aligned.m8n8.x4.shared.b16 {%0,%1,%2,%3}, [%4];"
                 : "=r"(r0), "=r"(r1), "=r"(r2), "=r"(r3) : "r"(addr));
}

// ---------------- W pre-transpose: fp32 [k][n] -> fp16 [n][k] --------------
__global__ void k_prepW(const float* __restrict__ w0, const float* __restrict__ w1) {
    int idx = blockIdx.x * 256 + threadIdx.x;  // 0..32767
    if (idx < 16384) {
        int k = idx >> 7, nn = idx & 127;
        g_wt0[nn * 128 + k] = __float2half_rn(w0[idx]);
    } else {
        int j = idx - 16384;
        int k = j >> 7, nn = j & 127;
        g_wt1[nn * 128 + k] = __float2half_rn(w1[j]);
    }
}

// ---------------- init ----------------------------------------------------
__global__ void k_init(const int* __restrict__ w) {
    int i = blockIdx.x * blockDim.x + threadIdx.x;
    if (i < NN) g_deg[i] = 0;
    if (blockIdx.x == 0) {
        __shared__ int nz;
        if (threadIdx.x == 0) nz = 0;
        if (threadIdx.x < 256) {
            g_acc0[threadIdx.x] = 0.f;
            g_acc1[threadIdx.x] = 0.f;
        }
        __syncthreads();
        for (int j = threadIdx.x; j < 1024; j += blockDim.x)
            if (w[2 * j + 1] != 0) nz = 1;
        __syncthreads();
        if (threadIdx.x == 0) g_is64 = nz ? 0 : 1;
    }
}

// ---------------- CSR build ------------------------------------------------
__global__ void k_count(const int* __restrict__ w) {
    int t = blockIdx.x * blockDim.x + threadIdx.x;
    int base = t * 4;
    int is64 = g_is64;
    #pragma unroll
    for (int i = 0; i < 4; i++) {
        int e = base + i;
        if (e < EE) {
            int d = is64 ? w[2 * EE + 2 * e] : w[EE + e];
            if ((unsigned)d >= NN) d = 0;
            atomicAdd(&g_deg[d], 1);
        }
    }
}

__global__ void k_scan1() {
    __shared__ int sh[1024];
    int t = threadIdx.x;
    int i = blockIdx.x * 1024 + t;
    int v = (i < NN) ? g_deg[i] : 0;
    sh[t] = v;
    __syncthreads();
    #pragma unroll
    for (int off = 1; off < 1024; off <<= 1) {
        int x = (t >= off) ? sh[t - off] : 0;
        __syncthreads();
        sh[t] += x;
        __syncthreads();
    }
    if (i < NN) g_rowptr[i] = sh[t] - v;
    if (t == 1023) g_bsum[blockIdx.x] = sh[t];
}

__global__ void k_scan23(int nb) {
    __shared__ int pre[128];
    __shared__ int total;
    int t = threadIdx.x;
    if (t < nb) pre[t] = g_bsum[t];
    __syncthreads();
    if (t == 0) {
        int run = 0;
        for (int b = 0; b < nb; b++) {
            int x = pre[b];
            pre[b] = run;
            run += x;
        }
        total = run;
    }
    __syncthreads();
    int i = blockIdx.x * blockDim.x + t;
    if (i < NN) {
        int v = g_rowptr[i] + pre[i >> 10];
        g_rowptr[i] = v;
        g_cursor[i] = v;
    }
    if (i == 0) g_rowptr[NN] = total;
}

__global__ void k_scatter(const int* __restrict__ w) {
    int t = blockIdx.x * blockDim.x + threadIdx.x;
    int base = t * 4;
    int is64 = g_is64;
    #pragma unroll
    for (int i = 0; i < 4; i++) {
        int e = base + i;
        if (e < EE) {
            int s, d;
            if (is64) {
                s = w[2 * e];
                d = w[2 * EE + 2 * e];
            } else {
                s = w[e];
                d = w[EE + e];
            }
            if ((unsigned)s >= NN) s = 0;
            if ((unsigned)d >= NN) d = 0;
            int pos = atomicAdd(&g_cursor[d], 1);
            g_perm_src[pos] = s;
            g_perm_dst[pos] = d;
        }
    }
}

// ---------------- edge weights ---------------------------------------------
__global__ void ew2_kernel() {
    int t = blockIdx.x * blockDim.x + threadIdx.x;
    int base = t * 4;
    #pragma unroll
    for (int i = 0; i < 4; i++) {
        int p = base + i;
        if (p < EE) {
            int s = g_perm_src[p];
            int d = g_perm_dst[p];
            float2 as = *(const float2*)&g_als[s * 2];
            float2 ad = *(const float2*)&g_ald[d * 2];
            float v0 = as.x + ad.x; v0 = v0 > 0.f ? v0 : SLOPE * v0;
            float v1 = as.y + ad.y; v1 = v1 > 0.f ? v1 : SLOPE * v1;
            g_ew0[p] = __expf(v0);
            g_ew1[p] = __expf(v1);
        }
    }
}

__global__ void ew1_kernel() {
    int t = blockIdx.x * blockDim.x + threadIdx.x;
    int base = t * 4;
    #pragma unroll
    for (int i = 0; i < 4; i++) {
        int p = base + i;
        if (p < EE) {
            int s = g_perm_src[p];
            int d = g_perm_dst[p];
            float v0 = g_als[s] + g_ald[d];
            v0 = v0 > 0.f ? v0 : SLOPE * v0;
            g_ew0[p] = __expf(v0);
        }
    }
}

// ---------------- tensor-core GEMM 128x128 v2: ldmatrix, 16 warps ----------
// Warp grid 8x2: warp owns 16 rows x 64 cols (head = wc). A staged fp32->fp16,
// B copied from pre-transposed fp16 W. Fused BN+ReLU input, fp16 out, al.
template <bool TRANS>
__global__ __launch_bounds__(512)
void gemm128_tc(const float* __restrict__ A, const __half* __restrict__ WT,
                __half2* __restrict__ C,
                const float* __restrict__ asrc, const float* __restrict__ adst,
                int n) {
    __shared__ __half sA[128 * 72];
    __shared__ __half sB[128 * 72];

    int tid = threadIdx.x;
    int lane = tid & 31, wid = tid >> 5;
    int wr = wid >> 1, wc = wid & 1;
    int g = lane >> 2, tig = lane & 3;
    int row0 = blockIdx.x * 128;

    float c[8][4];
    #pragma unroll
    for (int t = 0; t < 8; t++)
        #pragma unroll
        for (int j = 0; j < 4; j++) c[t][j] = 0.f;

    // hoisted ldmatrix lane addressing
    int a_row = wr * 16 + (lane & 15);
    int a_koff = (lane >> 4) * 8;
    int b_rowoff = ((lane >> 4) & 1) * 8 + (lane & 7);
    int b_koff = ((lane >> 3) & 1) * 8;

    #pragma unroll
    for (int p = 0; p < 2; p++) {
        int k0 = p * 64;
        __syncthreads();
        // stage A: rows x 64k, STS.128 conflict-free
        #pragma unroll
        for (int i = 0; i < 2; i++) {
            int idx = tid + i * 512;          // 0..1023
            int r = idx >> 3, q = idx & 7;
            int gr = row0 + r;
            float4 v1 = make_float4(0.f, 0.f, 0.f, 0.f);
            float4 v2 = make_float4(0.f, 0.f, 0.f, 0.f);
            if (gr < n) {
                v1 = *(const float4*)&A[(size_t)gr * 128 + k0 + q * 8];
                v2 = *(const float4*)&A[(size_t)gr * 128 + k0 + q * 8 + 4];
            }
            if (TRANS) {
                int f = k0 + q * 8;
                v1.x = fmaxf(v1.x * g_stats[f + 0] + g_stats[128 + f + 0], 0.f);
                v1.y = fmaxf(v1.y * g_stats[f + 1] + g_stats[128 + f + 1], 0.f);
                v1.z = fmaxf(v1.z * g_stats[f + 2] + g_stats[128 + f + 2], 0.f);
                v1.w = fmaxf(v1.w * g_stats[f + 3] + g_stats[128 + f + 3], 0.f);
                v2.x = fmaxf(v2.x * g_stats[f + 4] + g_stats[128 + f + 4], 0.f);
                v2.y = fmaxf(v2.y * g_stats[f + 5] + g_stats[128 + f + 5], 0.f);
                v2.z = fmaxf(v2.z * g_stats[f + 6] + g_stats[128 + f + 6], 0.f);
                v2.w = fmaxf(v2.w * g_stats[f + 7] + g_stats[128 + f + 7], 0.f);
            }
            __half2 hh[4];
            hh[0] = __floats2half2_rn(v1.x, v1.y);
            hh[1] = __floats2half2_rn(v1.z, v1.w);
            hh[2] = __floats2half2_rn(v2.x, v2.y);
            hh[3] = __floats2half2_rn(v2.z, v2.w);
            *(uint4*)&sA[r * 72 + q * 8] = *(uint4*)hh;
        }
        // stage B: plain fp16 copy from WT, STS.128 conflict-free
        #pragma unroll
        for (int i = 0; i < 2; i++) {
            int idx = tid + i * 512;
            int nn = idx >> 3, q = idx & 7;
            *(uint4*)&sB[nn * 72 + q * 8] =
                *(const uint4*)&WT[nn * 128 + k0 + q * 8];
        }
        __syncthreads();
        #pragma unroll
        for (int kc = 0; kc < 4; kc++) {
            int kb = kc * 16;
            unsigned a0, a1, a2, a3;
            ldsm4(a0, a1, a2, a3, smem_u32(&sA[a_row * 72 + kb + a_koff]));
            #pragma unroll
            for (int tt = 0; tt < 4; tt++) {
                int T0 = wc * 64 + tt * 16;
                unsigned b0, b1, b2, b3;
                ldsm4(b0, b1, b2, b3, smem_u32(&sB[(T0 + b_rowoff) * 72 + kb + b_koff]));
                mma16816(c[tt * 2 + 0], a0, a1, a2, a3, b0, b1);
                mma16816(c[tt * 2 + 1], a0, a1, a2, a3, b2, b3);
            }
        }
    }

    // epilogue: fp16 store + fused attention logits (this warp's head = wc)
    int r0 = row0 + wr * 16 + g;
    int r1 = r0 + 8;
    bool v0 = r0 < n, v1 = r1 < n;
    float s0 = 0.f, d0 = 0.f, s1 = 0.f, d1 = 0.f;

    #pragma unroll
    for (int t = 0; t < 8; t++) {
        int col = wc * 64 + t * 8 + 2 * tig;
        float as0 = asrc[col], as1 = asrc[col + 1];
        float ad0 = adst[col], ad1 = adst[col + 1];
        s0 += c[t][0] * as0 + c[t][1] * as1;
        d0 += c[t][0] * ad0 + c[t][1] * ad1;
        s1 += c[t][2] * as0 + c[t][3] * as1;
        d1 += c[t][2] * ad0 + c[t][3] * ad1;
        int ci = wc * 32 + t * 4 + tig;
        if (v0) C[(size_t)r0 * 64 + ci] = __floats2half2_rn(c[t][0], c[t][1]);
        if (v1) C[(size_t)r1 * 64 + ci] = __floats2half2_rn(c[t][2], c[t][3]);
    }
    #pragma unroll
    for (int o = 1; o < 4; o <<= 1) {
        s0 += __shfl_xor_sync(0xffffffffu, s0, o);
        d0 += __shfl_xor_sync(0xffffffffu, d0, o);
        s1 += __shfl_xor_sync(0xffffffffu, s1, o);
        d1 += __shfl_xor_sync(0xffffffffu, d1, o);
    }
    if (tig == 0) {
        if (v0) { g_als[r0 * 2 + wc] = s0; g_ald[r0 * 2 + wc] = d0; }
        if (v1) { g_als[r1 * 2 + wc] = s1; g_ald[r1 * 2 + wc] = d1; }
    }
}

// ---------------- small GEMM (layer 2, NC=40): BN+ReLU in, fp16 out, al ----
__global__ __launch_bounds__(256)
void gemm40_kernel(const float* __restrict__ A, const float* __restrict__ W,
                   __half* __restrict__ C,
                   const float* __restrict__ asrc, const float* __restrict__ adst,
                   int n) {
    constexpr int BM = 64, BK = 32, K = 128, NC = 40, NCPAD = 64;
    constexpr int CPT = NCPAD / 16;
    __shared__ float sA[BM][BK + 1];
    __shared__ float sW[BK][NCPAD];

    int tid = threadIdx.x;
    int tx = tid & 15, ty = tid >> 4;
    int row0 = blockIdx.x * BM;

    float acc[4][CPT];
    #pragma unroll
    for (int r = 0; r < 4; r++)
        #pragma unroll
        for (int c = 0; c < CPT; c++) acc[r][c] = 0.f;

    for (int k0 = 0; k0 < K; k0 += BK) {
        #pragma unroll
        for (int i = 0; i < (BM * BK) / 256; i++) {
            int e = tid + i * 256;
            int r = e >> 5, c = e & 31;
            int gr = row0 + r;
            float v = (gr < n) ? A[(size_t)gr * K + k0 + c] : 0.f;
            int f = k0 + c;
            v = fmaxf(v * g_stats[f] + g_stats[128 + f], 0.f);
            sA[r][c] = v;
        }
        #pragma unroll
        for (int i = 0; i < (BK * NCPAD) / 256; i++) {
            int e = tid + i * 256;
            int kk = e / NCPAD, c = e % NCPAD;
            sW[kk][c] = (c < NC) ? W[(size_t)(k0 + kk) * NC + c] : 0.f;
        }
        __syncthreads();
        #pragma unroll
        for (int k = 0; k < BK; k++) {
            float a0 = sA[ty * 4 + 0][k];
            float a1 = sA[ty * 4 + 1][k];
            float a2 = sA[ty * 4 + 2][k];
            float a3 = sA[ty * 4 + 3][k];
            #pragma unroll
            for (int c = 0; c < CPT; c++) {
                float w = sW[k][tx + c * 16];
                acc[0][c] += a0 * w;
                acc[1][c] += a1 * w;
                acc[2][c] += a2 * w;
                acc[3][c] += a3 * w;
            }
        }
        __syncthreads();
    }
    float asr[CPT], adr[CPT];
    #pragma unroll
    for (int c = 0; c < CPT; c++) {
        int col = tx + c * 16;
        asr[c] = (col < NC) ? asrc[col] : 0.f;
        adr[c] = (col < NC) ? adst[col] : 0.f;
    }
    #pragma unroll
    for (int r = 0; r < 4; r++) {
        int gr = row0 + ty * 4 + r;
        float s = 0.f, d = 0.f;
        #pragma unroll
        for (int c = 0; c < CPT; c++) {
            int col = tx + c * 16;
            if (gr < n && col < NC) C[(size_t)gr * NC + col] = __float2half_rn(acc[r][c]);
            s += acc[r][c] * asr[c];
            d += acc[r][c] * adr[c];
        }
        #pragma unroll
        for (int o = 1; o < 16; o <<= 1) {
            s += __shfl_xor_sync(0xffffffffu, s, o);
            d += __shfl_xor_sync(0xffffffffu, d, o);
        }
        if (tx == 0 && gr < n) {
            g_als[gr] = s;
            g_ald[gr] = d;
        }
    }
}

// ---------------- gather H=2: 8 nodes/warp, fused BN statistics ------------
__global__ __launch_bounds__(256)
void gather2_kernel(const __half2* __restrict__ hin,
                    const float* __restrict__ bias,
                    float* __restrict__ out,
                    float* __restrict__ accg) {
    __shared__ float sacc[256];
    int tid = threadIdx.x;
    sacc[tid] = 0.f;
    __syncthreads();

    int lane = tid & 31;
    int warp0 = (blockIdx.x * 256 + tid) >> 5;
    int head = lane >> 4;
    int sub = lane & 15;
    int hsel = head << 4;
    int col2 = lane * 2;
    const float* ewp = head ? g_ew1 : g_ew0;
    float4 b4 = *(const float4*)&bias[lane * 4];

    float4 st = make_float4(0.f, 0.f, 0.f, 0.f);
    float4 st2 = make_float4(0.f, 0.f, 0.f, 0.f);

    for (int it = 0; it < 8; it++) {
        int gw = warp0 * 8 + it;
        if (gw >= NN) break;
        int rs = g_rowptr[gw];
        int deg = g_rowptr[gw + 1] - rs;

        float4 acc = make_float4(0.f, 0.f, 0.f, 0.f);
        float sum = 0.f;

        int p0 = sub;
        bool vv = p0 < deg;
        int sj = vv ? g_perm_src[rs + p0] : 0;
        float e = vv ? ewp[rs + p0] : 0.f;

        for (int base = 0; base < deg; base += 16) {
            int pn = base + 16 + sub;
            bool vn = pn < deg;
            int sjn = vn ? g_perm_src[rs + pn] : 0;
            float en = vn ? ewp[rs + pn] : 0.f;
            #pragma unroll
            for (int j = 0; j < 16; j++) {
                float w = __shfl_sync(0xffffffffu, e, hsel | j);
                int s = __shfl_sync(0xffffffffu, sj, j);
                sum += w;
                uint2 hv = *(const uint2*)&hin[(size_t)s * 64 + col2];
                float2 f0 = __half22float2(*(const __half2*)&hv.x);
                float2 f1 = __half22float2(*(const __half2*)&hv.y);
                acc.x += w * f0.x;
                acc.y += w * f0.y;
                acc.z += w * f1.x;
                acc.w += w * f1.y;
            }
            sj = sjn;
            e = en;
        }
        float idn = 1.f / (sum + 1e-16f);
        float4 o;
        o.x = acc.x * idn + b4.x;
        o.y = acc.y * idn + b4.y;
        o.z = acc.z * idn + b4.z;
        o.w = acc.w * idn + b4.w;
        *(float4*)&out[(size_t)gw * 128 + lane * 4] = o;
        st.x += o.x; st.y += o.y; st.z += o.z; st.w += o.w;
        st2.x += o.x * o.x; st2.y += o.y * o.y;
        st2.z += o.z * o.z; st2.w += o.w * o.w;
    }
    // flush per-warp stats to shared, then shared to global
    int col = lane * 4;
    atomicAdd(&sacc[col + 0], st.x);
    atomicAdd(&sacc[col + 1], st.y);
    atomicAdd(&sacc[col + 2], st.z);
    atomicAdd(&sacc[col + 3], st.w);
    atomicAdd(&sacc[128 + col + 0], st2.x);
    atomicAdd(&sacc[128 + col + 1], st2.y);
    atomicAdd(&sacc[128 + col + 2], st2.z);
    atomicAdd(&sacc[128 + col + 3], st2.w);
    __syncthreads();
    atomicAdd(&accg[tid], sacc[tid]);
}

// ---------------- gather H=1 (layer 2): 40 cols ----------------------------
__global__ __launch_bounds__(256)
void gather1_kernel(const __half* __restrict__ hin,
                    const float* __restrict__ bias,
                    float* __restrict__ out) {
    constexpr int F = 40;
    constexpr int NV = 10;
    int gw = (blockIdx.x * blockDim.x + threadIdx.x) >> 5;
    int lane = threadIdx.x & 31;
    if (gw >= NN) return;
    int rs = g_rowptr[gw];
    int deg = g_rowptr[gw + 1] - rs;
    bool act = lane < NV;
    int col = lane * 4;

    if (deg == 0) {
        if (act) *(float4*)&out[(size_t)gw * F + col] = *(const float4*)&bias[col];
        return;
    }

    float4 acc = make_float4(0.f, 0.f, 0.f, 0.f);
    float sum = 0.f;
    const __half2* h2 = (const __half2*)hin;

    int p0 = lane;
    bool vv = p0 < deg;
    int sj = vv ? g_perm_src[rs + p0] : 0;
    float e = vv ? g_ew0[rs + p0] : 0.f;

    for (int base = 0; base < deg; base += 32) {
        int pn = base + 32 + lane;
        bool vn = pn < deg;
        int sjn = vn ? g_perm_src[rs + pn] : 0;
        float en = vn ? g_ew0[rs + pn] : 0.f;
        #pragma unroll
        for (int j = 0; j < 32; j++) {
            float w = __shfl_sync(0xffffffffu, e, j);
            int s = __shfl_sync(0xffffffffu, sj, j);
            sum += w;
            if (act) {
                uint2 hv = *(const uint2*)&h2[(size_t)s * 20 + lane * 2];
                float2 f0 = __half22float2(*(const __half2*)&hv.x);
                float2 f1 = __half22float2(*(const __half2*)&hv.y);
                acc.x += w * f0.x;
                acc.y += w * f0.y;
                acc.z += w * f1.x;
                acc.w += w * f1.y;
            }
        }
        sj = sjn;
        e = en;
    }
    if (act) {
        float idn = 1.f / (sum + 1e-16f);
        float4 b4 = *(const float4*)&bias[col];
        float4 o;
        o.x = acc.x * idn + b4.x;
        o.y = acc.y * idn + b4.y;
        o.z = acc.z * idn + b4.z;
        o.w = acc.w * idn + b4.w;
        *(float4*)&out[(size_t)gw * F + col] = o;
    }
}

// ---------------- batch norm finalize --------------------------------------
__global__ void bn_final(const float* __restrict__ acc,
                         const float* __restrict__ g,
                         const float* __restrict__ beta, float inv_n) {
    int f = threadIdx.x;  // 128
    float mu = acc[f] * inv_n;
    float var = acc[128 + f] * inv_n - mu * mu;
    float sc = rsqrtf(var + BN_EPS) * g[f];
    float sh = beta[f] - mu * sc;
    g_stats[f] = sc;
    g_stats[128 + f] = sh;
}

// ---------------- launch ---------------------------------------------------
extern "C" void kernel_launch(void* const* d_in, const int* in_sizes, int n_in,
                              void* d_out, int out_size) {
    const float* x     = (const float*)d_in[0];
    const int*   eiw   = (const int*)d_in[1];
    const float* w0    = (const float*)d_in[2];
    const float* asrc0 = (const float*)d_in[3];
    const float* adst0 = (const float*)d_in[4];
    const float* b0    = (const float*)d_in[5];
    const float* gg0   = (const float*)d_in[6];
    const float* beta0 = (const float*)d_in[7];
    const float* w1    = (const float*)d_in[8];
    const float* asrc1 = (const float*)d_in[9];
    const float* adst1 = (const float*)d_in[10];
    const float* b1    = (const float*)d_in[11];
    const float* gg1   = (const float*)d_in[12];
    const float* beta1 = (const float*)d_in[13];
    const float* w2    = (const float*)d_in[14];
    const float* asrc2 = (const float*)d_in[15];
    const float* adst2 = (const float*)d_in[16];
    const float* b2    = (const float*)d_in[17];
    float* out = (float*)d_out;

    __half2* h16 = nullptr;
    __half *wt0 = nullptr, *wt1 = nullptr;
    float *bufB = nullptr, *acc0 = nullptr, *acc1 = nullptr;
    cudaGetSymbolAddress((void**)&h16, g_h16);
    cudaGetSymbolAddress((void**)&wt0, g_wt0);
    cudaGetSymbolAddress((void**)&wt1, g_wt1);
    cudaGetSymbolAddress((void**)&bufB, g_bufB);
    cudaGetSymbolAddress((void**)&acc0, g_acc0);
    cudaGetSymbolAddress((void**)&acc1, g_acc1);

    static cudaStream_t s2 = nullptr;
    static cudaEvent_t evFork = nullptr, evW = nullptr, evJoin = nullptr;
    if (s2 == nullptr) {
        cudaStreamCreateWithFlags(&s2, cudaStreamNonBlocking);
        cudaEventCreateWithFlags(&evFork, cudaEventDisableTiming);
        cudaEventCreateWithFlags(&evW, cudaEventDisableTiming);
        cudaEventCreateWithFlags(&evJoin, cudaEventDisableTiming);
    }

    const int nb = (NN + 1023) / 1024;
    const int gE4 = (EE / 4 + 255) / 256;
    const int gN = (NN + 255) / 256;
    const int gW = (NN * 32 + 255) / 256;            // warp-per-node (gather1)
    const int gW8 = ((NN + 7) / 8 * 32 + 255) / 256; // 8 nodes/warp (gather2)
    const int gM128 = (NN + 127) / 128;
    const int gM64 = (NN + 63) / 64;

    // ---- fork: W-prep + CSR on s2; gemm L0 on main at submission idx 3 ----
    cudaEventRecord(evFork, 0);
    cudaStreamWaitEvent(s2, evFork, 0);
    k_prepW<<<128, 256, 0, s2>>>(w0, w1);            // 0
    cudaEventRecord(evW, s2);
    k_init<<<gN, 256, 0, s2>>>(eiw);                 // 1
    k_count<<<gE4, 256, 0, s2>>>(eiw);               // 2
    cudaStreamWaitEvent(0, evW, 0);
    gemm128_tc<false><<<gM128, 512>>>(x, wt0, h16, asrc0, adst0, NN);  // 3 (profiled)
    k_scan1<<<nb, 1024, 0, s2>>>();                  // 4
    k_scan23<<<gN, 256, 0, s2>>>(nb);                // 5
    k_scatter<<<gE4, 256, 0, s2>>>(eiw);             // 6
    cudaEventRecord(evJoin, s2);
    cudaStreamWaitEvent(0, evJoin, 0);

    const float inv_n = 1.0f / (float)NN;

    // ---- layer 0 tail ----
    ew2_kernel<<<gE4, 256>>>();
    gather2_kernel<<<gW8, 256>>>(h16, b0, bufB, acc0);
    bn_final<<<1, 128>>>(acc0, gg0, beta0, inv_n);

    // ---- layer 1 ----
    gemm128_tc<true><<<gM128, 512>>>(bufB, wt1, h16, asrc1, adst1, NN);
    ew2_kernel<<<gE4, 256>>>();
    gather2_kernel<<<gW8, 256>>>(h16, b1, bufB, acc1);
    bn_final<<<1, 128>>>(acc1, gg1, beta1, inv_n);

    // ---- layer 2 ----
    gemm40_kernel<<<gM64, 256>>>(bufB, w2, (__half*)h16, asrc2, adst2, NN);
    ew1_kernel<<<gE4, 256>>>();
    gather1_kernel<<<gW, 256>>>((const __half*)h16, b2, out);
}

// round 17
// speedup vs baseline: 1.4727x; 1.1607x over previous
#include <cuda_runtime.h>
#include <cuda_fp16.h>
#include <math.h>

#define NN   100000
#define EE   1600000
#define BN_EPS 1e-5f
#define SLOPE 0.2f

// ---------------- scratch (device globals; no allocation allowed) ----------
__device__ __half2 g_h16[(size_t)NN * 64];   // gemm output h (fp16, 128/row)
__device__ __half2 g_hA[(size_t)NN * 64];    // gather output (fp16, 128/row)
__device__ float  g_als[NN * 2];
__device__ float  g_ald[NN * 2];
__device__ float  g_ew0[EE];
__device__ float  g_ew1[EE];
__device__ __half g_wt0[128 * 128];          // W0^T fp16 [n][k]
__device__ __half g_wt1[128 * 128];          // W1^T fp16 [n][k]
__device__ int    g_deg[NN];
__device__ int    g_rowptr[NN + 1];
__device__ int    g_cursor[NN];
__device__ int    g_perm_src[EE];
__device__ int    g_perm_dst[EE];
__device__ int    g_bsum[128];
__device__ int    g_is64;
__device__ float  g_acc0[256];
__device__ float  g_acc1[256];
__device__ float  g_stats[256];

__device__ __forceinline__ unsigned smem_u32(const void* p) {
    return (unsigned)__cvta_generic_to_shared(p);
}

__device__ __forceinline__ void mma16816(float* c,
                                         unsigned a0, unsigned a1, unsigned a2, unsigned a3,
                                         unsigned b0, unsigned b1) {
    asm("mma.sync.aligned.m16n8k16.row.col.f32.f16.f16.f32 "
        "{%0,%1,%2,%3}, {%4,%5,%6,%7}, {%8,%9}, {%0,%1,%2,%3};\n"
        : "+f"(c[0]), "+f"(c[1]), "+f"(c[2]), "+f"(c[3])
        : "r"(a0), "r"(a1), "r"(a2), "r"(a3), "r"(b0), "r"(b1));
}

__device__ __forceinline__ void ldsm4(unsigned& r0, unsigned& r1, unsigned& r2, unsigned& r3,
                                      unsigned addr) {
    asm volatile("ldmatrix.sync.aligned.m8n8.x4.shared.b16 {%0,%1,%2,%3}, [%4];"
                 : "=r"(r0), "=r"(r1), "=r"(r2), "=r"(r3) : "r"(addr));
}

// ---------------- W pre-transpose: fp32 [k][n] -> fp16 [n][k] --------------
__global__ void k_prepW(const float* __restrict__ w0, const float* __restrict__ w1) {
    int idx = blockIdx.x * 256 + threadIdx.x;  // 0..32767
    if (idx < 16384) {
        int k = idx >> 7, nn = idx & 127;
        g_wt0[nn * 128 + k] = __float2half_rn(w0[idx]);
    } else {
        int j = idx - 16384;
        int k = j >> 7, nn = j & 127;
        g_wt1[nn * 128 + k] = __float2half_rn(w1[j]);
    }
}

// ---------------- init ----------------------------------------------------
__global__ void k_init(const int* __restrict__ w) {
    int i = blockIdx.x * blockDim.x + threadIdx.x;
    if (i < NN) g_deg[i] = 0;
    if (blockIdx.x == 0) {
        __shared__ int nz;
        if (threadIdx.x == 0) nz = 0;
        if (threadIdx.x < 256) {
            g_acc0[threadIdx.x] = 0.f;
            g_acc1[threadIdx.x] = 0.f;
        }
        __syncthreads();
        for (int j = threadIdx.x; j < 1024; j += blockDim.x)
            if (w[2 * j + 1] != 0) nz = 1;
        __syncthreads();
        if (threadIdx.x == 0) g_is64 = nz ? 0 : 1;
    }
}

// ---------------- CSR build ------------------------------------------------
__global__ void k_count(const int* __restrict__ w) {
    int t = blockIdx.x * blockDim.x + threadIdx.x;
    int base = t * 4;
    int is64 = g_is64;
    #pragma unroll
    for (int i = 0; i < 4; i++) {
        int e = base + i;
        if (e < EE) {
            int d = is64 ? w[2 * EE + 2 * e] : w[EE + e];
            if ((unsigned)d >= NN) d = 0;
            atomicAdd(&g_deg[d], 1);
        }
    }
}

__global__ void k_scan1() {
    __shared__ int sh[1024];
    int t = threadIdx.x;
    int i = blockIdx.x * 1024 + t;
    int v = (i < NN) ? g_deg[i] : 0;
    sh[t] = v;
    __syncthreads();
    #pragma unroll
    for (int off = 1; off < 1024; off <<= 1) {
        int x = (t >= off) ? sh[t - off] : 0;
        __syncthreads();
        sh[t] += x;
        __syncthreads();
    }
    if (i < NN) g_rowptr[i] = sh[t] - v;
    if (t == 1023) g_bsum[blockIdx.x] = sh[t];
}

__global__ void k_scan23(int nb) {
    __shared__ int pre[128];
    __shared__ int total;
    int t = threadIdx.x;
    if (t < nb) pre[t] = g_bsum[t];
    __syncthreads();
    if (t == 0) {
        int run = 0;
        for (int b = 0; b < nb; b++) {
            int x = pre[b];
            pre[b] = run;
            run += x;
        }
        total = run;
    }
    __syncthreads();
    int i = blockIdx.x * blockDim.x + t;
    if (i < NN) {
        int v = g_rowptr[i] + pre[i >> 10];
        g_rowptr[i] = v;
        g_cursor[i] = v;
    }
    if (i == 0) g_rowptr[NN] = total;
}

__global__ void k_scatter(const int* __restrict__ w) {
    int t = blockIdx.x * blockDim.x + threadIdx.x;
    int base = t * 4;
    int is64 = g_is64;
    #pragma unroll
    for (int i = 0; i < 4; i++) {
        int e = base + i;
        if (e < EE) {
            int s, d;
            if (is64) {
                s = w[2 * e];
                d = w[2 * EE + 2 * e];
            } else {
                s = w[e];
                d = w[EE + e];
            }
            if ((unsigned)s >= NN) s = 0;
            if ((unsigned)d >= NN) d = 0;
            int pos = atomicAdd(&g_cursor[d], 1);
            g_perm_src[pos] = s;
            g_perm_dst[pos] = d;
        }
    }
}

// ---------------- edge weights ---------------------------------------------
__global__ void ew2_kernel() {
    int t = blockIdx.x * blockDim.x + threadIdx.x;
    int base = t * 4;
    #pragma unroll
    for (int i = 0; i < 4; i++) {
        int p = base + i;
        if (p < EE) {
            int s = g_perm_src[p];
            int d = g_perm_dst[p];
            float2 as = *(const float2*)&g_als[s * 2];
            float2 ad = *(const float2*)&g_ald[d * 2];
            float v0 = as.x + ad.x; v0 = v0 > 0.f ? v0 : SLOPE * v0;
            float v1 = as.y + ad.y; v1 = v1 > 0.f ? v1 : SLOPE * v1;
            g_ew0[p] = __expf(v0);
            g_ew1[p] = __expf(v1);
        }
    }
}

__global__ void ew1_kernel() {
    int t = blockIdx.x * blockDim.x + threadIdx.x;
    int base = t * 4;
    #pragma unroll
    for (int i = 0; i < 4; i++) {
        int p = base + i;
        if (p < EE) {
            int s = g_perm_src[p];
            int d = g_perm_dst[p];
            float v0 = g_als[s] + g_ald[d];
            v0 = v0 > 0.f ? v0 : SLOPE * v0;
            g_ew0[p] = __expf(v0);
        }
    }
}

// ---------------- tensor-core GEMM 128x128: ldmatrix, 16 warps -------------
// TRANS=false: A fp32 (input x). TRANS=true: A fp16 (gather output) with
// fused BN+ReLU during staging. Fused al epilogue; fp16 C.
template <bool TRANS>
__global__ __launch_bounds__(512)
void gemm128_tc(const void* __restrict__ Ap, const __half* __restrict__ WT,
                __half2* __restrict__ C,
                const float* __restrict__ asrc, const float* __restrict__ adst,
                int n) {
    __shared__ __half sA[128 * 72];
    __shared__ __half sB[128 * 72];

    int tid = threadIdx.x;
    int lane = tid & 31, wid = tid >> 5;
    int wr = wid >> 1, wc = wid & 1;
    int g = lane >> 2, tig = lane & 3;
    int row0 = blockIdx.x * 128;

    float c[8][4];
    #pragma unroll
    for (int t = 0; t < 8; t++)
        #pragma unroll
        for (int j = 0; j < 4; j++) c[t][j] = 0.f;

    int a_row = wr * 16 + (lane & 15);
    int a_koff = (lane >> 4) * 8;
    int b_rowoff = ((lane >> 4) & 1) * 8 + (lane & 7);
    int b_koff = ((lane >> 3) & 1) * 8;

    #pragma unroll
    for (int p = 0; p < 2; p++) {
        int k0 = p * 64;
        __syncthreads();
        // stage A
        #pragma unroll
        for (int i = 0; i < 2; i++) {
            int idx = tid + i * 512;          // 0..1023
            int r = idx >> 3, q = idx & 7;
            int gr = row0 + r;
            if (TRANS) {
                const __half2* Ah = (const __half2*)Ap;
                uint4 hv = make_uint4(0u, 0u, 0u, 0u);
                if (gr < n) hv = *(const uint4*)&Ah[(size_t)gr * 64 + (k0 >> 1) + q * 4];
                __half2* hp = (__half2*)&hv;
                int f = k0 + q * 8;
                #pragma unroll
                for (int j = 0; j < 4; j++) {
                    float2 fv = __half22float2(hp[j]);
                    fv.x = fmaxf(fv.x * g_stats[f + 2 * j] + g_stats[128 + f + 2 * j], 0.f);
                    fv.y = fmaxf(fv.y * g_stats[f + 2 * j + 1] + g_stats[128 + f + 2 * j + 1], 0.f);
                    hp[j] = __floats2half2_rn(fv.x, fv.y);
                }
                *(uint4*)&sA[r * 72 + q * 8] = hv;
            } else {
                const float* A = (const float*)Ap;
                float4 v1 = make_float4(0.f, 0.f, 0.f, 0.f);
                float4 v2 = make_float4(0.f, 0.f, 0.f, 0.f);
                if (gr < n) {
                    v1 = *(const float4*)&A[(size_t)gr * 128 + k0 + q * 8];
                    v2 = *(const float4*)&A[(size_t)gr * 128 + k0 + q * 8 + 4];
                }
                __half2 hh[4];
                hh[0] = __floats2half2_rn(v1.x, v1.y);
                hh[1] = __floats2half2_rn(v1.z, v1.w);
                hh[2] = __floats2half2_rn(v2.x, v2.y);
                hh[3] = __floats2half2_rn(v2.z, v2.w);
                *(uint4*)&sA[r * 72 + q * 8] = *(uint4*)hh;
            }
        }
        // stage B (pre-transposed fp16 copy)
        #pragma unroll
        for (int i = 0; i < 2; i++) {
            int idx = tid + i * 512;
            int nn = idx >> 3, q = idx & 7;
            *(uint4*)&sB[nn * 72 + q * 8] =
                *(const uint4*)&WT[nn * 128 + k0 + q * 8];
        }
        __syncthreads();
        #pragma unroll
        for (int kc = 0; kc < 4; kc++) {
            int kb = kc * 16;
            unsigned a0, a1, a2, a3;
            ldsm4(a0, a1, a2, a3, smem_u32(&sA[a_row * 72 + kb + a_koff]));
            #pragma unroll
            for (int tt = 0; tt < 4; tt++) {
                int T0 = wc * 64 + tt * 16;
                unsigned b0, b1, b2, b3;
                ldsm4(b0, b1, b2, b3, smem_u32(&sB[(T0 + b_rowoff) * 72 + kb + b_koff]));
                mma16816(c[tt * 2 + 0], a0, a1, a2, a3, b0, b1);
                mma16816(c[tt * 2 + 1], a0, a1, a2, a3, b2, b3);
            }
        }
    }

    // epilogue
    int r0 = row0 + wr * 16 + g;
    int r1 = r0 + 8;
    bool v0 = r0 < n, v1 = r1 < n;
    float s0 = 0.f, d0 = 0.f, s1 = 0.f, d1 = 0.f;

    #pragma unroll
    for (int t = 0; t < 8; t++) {
        int col = wc * 64 + t * 8 + 2 * tig;
        float as0 = asrc[col], as1 = asrc[col + 1];
        float ad0 = adst[col], ad1 = adst[col + 1];
        s0 += c[t][0] * as0 + c[t][1] * as1;
        d0 += c[t][0] * ad0 + c[t][1] * ad1;
        s1 += c[t][2] * as0 + c[t][3] * as1;
        d1 += c[t][2] * ad0 + c[t][3] * ad1;
        int ci = wc * 32 + t * 4 + tig;
        if (v0) C[(size_t)r0 * 64 + ci] = __floats2half2_rn(c[t][0], c[t][1]);
        if (v1) C[(size_t)r1 * 64 + ci] = __floats2half2_rn(c[t][2], c[t][3]);
    }
    #pragma unroll
    for (int o = 1; o < 4; o <<= 1) {
        s0 += __shfl_xor_sync(0xffffffffu, s0, o);
        d0 += __shfl_xor_sync(0xffffffffu, d0, o);
        s1 += __shfl_xor_sync(0xffffffffu, s1, o);
        d1 += __shfl_xor_sync(0xffffffffu, d1, o);
    }
    if (tig == 0) {
        if (v0) { g_als[r0 * 2 + wc] = s0; g_ald[r0 * 2 + wc] = d0; }
        if (v1) { g_als[r1 * 2 + wc] = s1; g_ald[r1 * 2 + wc] = d1; }
    }
}

// ---------------- small GEMM (layer 2, NC=40): fp16 A, BN+ReLU, fp16 C, al -
__global__ __launch_bounds__(256)
void gemm40_kernel(const __half* __restrict__ A, const float* __restrict__ W,
                   __half* __restrict__ C,
                   const float* __restrict__ asrc, const float* __restrict__ adst,
                   int n) {
    constexpr int BM = 64, BK = 32, K = 128, NC = 40, NCPAD = 64;
    constexpr int CPT = NCPAD / 16;
    __shared__ float sA[BM][BK + 1];
    __shared__ float sW[BK][NCPAD];

    int tid = threadIdx.x;
    int tx = tid & 15, ty = tid >> 4;
    int row0 = blockIdx.x * BM;

    float acc[4][CPT];
    #pragma unroll
    for (int r = 0; r < 4; r++)
        #pragma unroll
        for (int c = 0; c < CPT; c++) acc[r][c] = 0.f;

    for (int k0 = 0; k0 < K; k0 += BK) {
        #pragma unroll
        for (int i = 0; i < (BM * BK) / 256; i++) {
            int e = tid + i * 256;
            int r = e >> 5, c = e & 31;
            int gr = row0 + r;
            float v = (gr < n) ? __half2float(A[(size_t)gr * K + k0 + c]) : 0.f;
            int f = k0 + c;
            v = fmaxf(v * g_stats[f] + g_stats[128 + f], 0.f);
            sA[r][c] = v;
        }
        #pragma unroll
        for (int i = 0; i < (BK * NCPAD) / 256; i++) {
            int e = tid + i * 256;
            int kk = e / NCPAD, c = e % NCPAD;
            sW[kk][c] = (c < NC) ? W[(size_t)(k0 + kk) * NC + c] : 0.f;
        }
        __syncthreads();
        #pragma unroll
        for (int k = 0; k < BK; k++) {
            float a0 = sA[ty * 4 + 0][k];
            float a1 = sA[ty * 4 + 1][k];
            float a2 = sA[ty * 4 + 2][k];
            float a3 = sA[ty * 4 + 3][k];
            #pragma unroll
            for (int c = 0; c < CPT; c++) {
                float w = sW[k][tx + c * 16];
                acc[0][c] += a0 * w;
                acc[1][c] += a1 * w;
                acc[2][c] += a2 * w;
                acc[3][c] += a3 * w;
            }
        }
        __syncthreads();
    }
    float asr[CPT], adr[CPT];
    #pragma unroll
    for (int c = 0; c < CPT; c++) {
        int col = tx + c * 16;
        asr[c] = (col < NC) ? asrc[col] : 0.f;
        adr[c] = (col < NC) ? adst[col] : 0.f;
    }
    #pragma unroll
    for (int r = 0; r < 4; r++) {
        int gr = row0 + ty * 4 + r;
        float s = 0.f, d = 0.f;
        #pragma unroll
        for (int c = 0; c < CPT; c++) {
            int col = tx + c * 16;
            if (gr < n && col < NC) C[(size_t)gr * NC + col] = __float2half_rn(acc[r][c]);
            s += acc[r][c] * asr[c];
            d += acc[r][c] * adr[c];
        }
        #pragma unroll
        for (int o = 1; o < 16; o <<= 1) {
            s += __shfl_xor_sync(0xffffffffu, s, o);
            d += __shfl_xor_sync(0xffffffffu, d, o);
        }
        if (tx == 0 && gr < n) {
            g_als[gr] = s;
            g_ald[gr] = d;
        }
    }
}

// ---------------- gather H=2: 4 nodes/warp, fp16 out, fused BN stats -------
__global__ __launch_bounds__(256)
void gather2_kernel(const __half2* __restrict__ hin,
                    const float* __restrict__ bias,
                    __half2* __restrict__ outh,
                    float* __restrict__ accg) {
    __shared__ float sacc[256];
    int tid = threadIdx.x;
    sacc[tid] = 0.f;
    __syncthreads();

    int lane = tid & 31;
    int warp0 = (blockIdx.x * 256 + tid) >> 5;
    int head = lane >> 4;
    int sub = lane & 15;
    int hsel = head << 4;
    int col2 = lane * 2;
    const float* ewp = head ? g_ew1 : g_ew0;
    float4 b4 = *(const float4*)&bias[lane * 4];

    float4 st = make_float4(0.f, 0.f, 0.f, 0.f);
    float4 st2 = make_float4(0.f, 0.f, 0.f, 0.f);

    #pragma unroll
    for (int it = 0; it < 4; it++) {
        int gw = warp0 * 4 + it;
        if (gw >= NN) break;
        int rs = g_rowptr[gw];
        int deg = g_rowptr[gw + 1] - rs;

        float4 acc = make_float4(0.f, 0.f, 0.f, 0.f);
        float sum = 0.f;

        int p0 = sub;
        bool vv = p0 < deg;
        int sj = vv ? g_perm_src[rs + p0] : 0;
        float e = vv ? ewp[rs + p0] : 0.f;

        for (int base = 0; base < deg; base += 16) {
            int pn = base + 16 + sub;
            bool vn = pn < deg;
            int sjn = vn ? g_perm_src[rs + pn] : 0;
            float en = vn ? ewp[rs + pn] : 0.f;
            #pragma unroll
            for (int j = 0; j < 16; j++) {
                float w = __shfl_sync(0xffffffffu, e, hsel | j);
                int s = __shfl_sync(0xffffffffu, sj, j);
                sum += w;
                uint2 hv = *(const uint2*)&hin[(size_t)s * 64 + col2];
                float2 f0 = __half22float2(*(const __half2*)&hv.x);
                float2 f1 = __half22float2(*(const __half2*)&hv.y);
                acc.x += w * f0.x;
                acc.y += w * f0.y;
                acc.z += w * f1.x;
                acc.w += w * f1.y;
            }
            sj = sjn;
            e = en;
        }
        float idn = 1.f / (sum + 1e-16f);
        float4 o;
        o.x = acc.x * idn + b4.x;
        o.y = acc.y * idn + b4.y;
        o.z = acc.z * idn + b4.z;
        o.w = acc.w * idn + b4.w;
        __half2 h01 = __floats2half2_rn(o.x, o.y);
        __half2 h23 = __floats2half2_rn(o.z, o.w);
        uint2 u;
        u.x = *(unsigned*)&h01;
        u.y = *(unsigned*)&h23;
        *(uint2*)&outh[(size_t)gw * 64 + col2] = u;
        st.x += o.x; st.y += o.y; st.z += o.z; st.w += o.w;
        st2.x += o.x * o.x; st2.y += o.y * o.y;
        st2.z += o.z * o.z; st2.w += o.w * o.w;
    }
    int col = lane * 4;
    atomicAdd(&sacc[col + 0], st.x);
    atomicAdd(&sacc[col + 1], st.y);
    atomicAdd(&sacc[col + 2], st.z);
    atomicAdd(&sacc[col + 3], st.w);
    atomicAdd(&sacc[128 + col + 0], st2.x);
    atomicAdd(&sacc[128 + col + 1], st2.y);
    atomicAdd(&sacc[128 + col + 2], st2.z);
    atomicAdd(&sacc[128 + col + 3], st2.w);
    __syncthreads();
    atomicAdd(&accg[tid], sacc[tid]);
}

// ---------------- gather H=1 (layer 2): 40 cols, fp32 out ------------------
__global__ __launch_bounds__(256)
void gather1_kernel(const __half* __restrict__ hin,
                    const float* __restrict__ bias,
                    float* __restrict__ out) {
    constexpr int F = 40;
    constexpr int NV = 10;
    int gw = (blockIdx.x * blockDim.x + threadIdx.x) >> 5;
    int lane = threadIdx.x & 31;
    if (gw >= NN) return;
    int rs = g_rowptr[gw];
    int deg = g_rowptr[gw + 1] - rs;
    bool act = lane < NV;
    int col = lane * 4;

    if (deg == 0) {
        if (act) *(float4*)&out[(size_t)gw * F + col] = *(const float4*)&bias[col];
        return;
    }

    float4 acc = make_float4(0.f, 0.f, 0.f, 0.f);
    float sum = 0.f;
    const __half2* h2 = (const __half2*)hin;

    int p0 = lane;
    bool vv = p0 < deg;
    int sj = vv ? g_perm_src[rs + p0] : 0;
    float e = vv ? g_ew0[rs + p0] : 0.f;

    for (int base = 0; base < deg; base += 32) {
        int pn = base + 32 + lane;
        bool vn = pn < deg;
        int sjn = vn ? g_perm_src[rs + pn] : 0;
        float en = vn ? g_ew0[rs + pn] : 0.f;
        #pragma unroll
        for (int j = 0; j < 32; j++) {
            float w = __shfl_sync(0xffffffffu, e, j);
            int s = __shfl_sync(0xffffffffu, sj, j);
            sum += w;
            if (act) {
                uint2 hv = *(const uint2*)&h2[(size_t)s * 20 + lane * 2];
                float2 f0 = __half22float2(*(const __half2*)&hv.x);
                float2 f1 = __half22float2(*(const __half2*)&hv.y);
                acc.x += w * f0.x;
                acc.y += w * f0.y;
                acc.z += w * f1.x;
                acc.w += w * f1.y;
            }
        }
        sj = sjn;
        e = en;
    }
    if (act) {
        float idn = 1.f / (sum + 1e-16f);
        float4 b4 = *(const float4*)&bias[col];
        float4 o;
        o.x = acc.x * idn + b4.x;
        o.y = acc.y * idn + b4.y;
        o.z = acc.z * idn + b4.z;
        o.w = acc.w * idn + b4.w;
        *(float4*)&out[(size_t)gw * F + col] = o;
    }
}

// ---------------- batch norm finalize --------------------------------------
__global__ void bn_final(const float* __restrict__ acc,
                         const float* __restrict__ g,
                         const float* __restrict__ beta, float inv_n) {
    int f = threadIdx.x;  // 128
    float mu = acc[f] * inv_n;
    float var = acc[128 + f] * inv_n - mu * mu;
    float sc = rsqrtf(var + BN_EPS) * g[f];
    float sh = beta[f] - mu * sc;
    g_stats[f] = sc;
    g_stats[128 + f] = sh;
}

// ---------------- launch ---------------------------------------------------
extern "C" void kernel_launch(void* const* d_in, const int* in_sizes, int n_in,
                              void* d_out, int out_size) {
    const float* x     = (const float*)d_in[0];
    const int*   eiw   = (const int*)d_in[1];
    const float* w0    = (const float*)d_in[2];
    const float* asrc0 = (const float*)d_in[3];
    const float* adst0 = (const float*)d_in[4];
    const float* b0    = (const float*)d_in[5];
    const float* gg0   = (const float*)d_in[6];
    const float* beta0 = (const float*)d_in[7];
    const float* w1    = (const float*)d_in[8];
    const float* asrc1 = (const float*)d_in[9];
    const float* adst1 = (const float*)d_in[10];
    const float* b1    = (const float*)d_in[11];
    const float* gg1   = (const float*)d_in[12];
    const float* beta1 = (const float*)d_in[13];
    const float* w2    = (const float*)d_in[14];
    const float* asrc2 = (const float*)d_in[15];
    const float* adst2 = (const float*)d_in[16];
    const float* b2    = (const float*)d_in[17];
    float* out = (float*)d_out;

    __half2 *h16 = nullptr, *hA = nullptr;
    __half *wt0 = nullptr, *wt1 = nullptr;
    float *acc0 = nullptr, *acc1 = nullptr;
    cudaGetSymbolAddress((void**)&h16, g_h16);
    cudaGetSymbolAddress((void**)&hA, g_hA);
    cudaGetSymbolAddress((void**)&wt0, g_wt0);
    cudaGetSymbolAddress((void**)&wt1, g_wt1);
    cudaGetSymbolAddress((void**)&acc0, g_acc0);
    cudaGetSymbolAddress((void**)&acc1, g_acc1);

    static cudaStream_t s2 = nullptr;
    static cudaEvent_t evFork = nullptr, evW = nullptr, evJoin = nullptr;
    if (s2 == nullptr) {
        cudaStreamCreateWithFlags(&s2, cudaStreamNonBlocking);
        cudaEventCreateWithFlags(&evFork, cudaEventDisableTiming);
        cudaEventCreateWithFlags(&evW, cudaEventDisableTiming);
        cudaEventCreateWithFlags(&evJoin, cudaEventDisableTiming);
    }

    const int nb = (NN + 1023) / 1024;
    const int gE4 = (EE / 4 + 255) / 256;
    const int gN = (NN + 255) / 256;
    const int gW = (NN * 32 + 255) / 256;             // warp-per-node (gather1)
    const int gW4 = (((NN + 3) / 4) * 32 + 255) / 256; // 4 nodes/warp (gather2)
    const int gM128 = (NN + 127) / 128;
    const int gM64 = (NN + 63) / 64;

    // ---- fork: W-prep + CSR on s2; gemm L0 on main (profiled slot) ----
    cudaEventRecord(evFork, 0);
    cudaStreamWaitEvent(s2, evFork, 0);
    k_prepW<<<128, 256, 0, s2>>>(w0, w1);
    cudaEventRecord(evW, s2);
    k_init<<<gN, 256, 0, s2>>>(eiw);
    k_count<<<gE4, 256, 0, s2>>>(eiw);
    cudaStreamWaitEvent(0, evW, 0);
    gemm128_tc<false><<<gM128, 512>>>(x, wt0, h16, asrc0, adst0, NN);
    k_scan1<<<nb, 1024, 0, s2>>>();
    k_scan23<<<gN, 256, 0, s2>>>(nb);
    k_scatter<<<gE4, 256, 0, s2>>>(eiw);
    cudaEventRecord(evJoin, s2);
    cudaStreamWaitEvent(0, evJoin, 0);

    const float inv_n = 1.0f / (float)NN;

    // ---- layer 0 tail ----
    ew2_kernel<<<gE4, 256>>>();
    gather2_kernel<<<gW4, 256>>>(h16, b0, hA, acc0);
    bn_final<<<1, 128>>>(acc0, gg0, beta0, inv_n);

    // ---- layer 1 ----
    gemm128_tc<true><<<gM128, 512>>>(hA, wt1, h16, asrc1, adst1, NN);
    ew2_kernel<<<gE4, 256>>>();
    gather2_kernel<<<gW4, 256>>>(h16, b1, hA, acc1);
    bn_final<<<1, 128>>>(acc1, gg1, beta1, inv_n);

    // ---- layer 2 ----
    gemm40_kernel<<<gM64, 256>>>((const __half*)hA, w2, (__half*)h16, asrc2, adst2, NN);
    ew1_kernel<<<gE4, 256>>>();
    gather1_kernel<<<gW, 256>>>((const __half*)h16, b2, out);
}